// round 3
// baseline (speedup 1.0000x reference)
#include <cuda_runtime.h>
#include <cstdint>

// P=8, B=4, C=32, H=256, W=256, M1=M2=32
// rows R = P*B*C*H = 262144 ; pbc = P*B*C = 1024 ; cols (pbc,y) = 32768

typedef unsigned long long ull;

__device__ __forceinline__ void ffma2(ull& c, ull a, ull b) {
    asm("fma.rn.f32x2 %0, %1, %2, %3;" : "=l"(c) : "l"(a), "l"(b), "l"(c));
}
__device__ __forceinline__ ull dup2(float x) {
    ull r;
    asm("mov.b64 %0, {%1, %1};" : "=l"(r) : "f"(x));
    return r;
}
__device__ __forceinline__ float2 unp2(ull v) {
    float2 f;
    asm("mov.b64 {%0, %1}, %2;" : "=f"(f.x), "=f"(f.y) : "l"(v));
    return f;
}

// ---------------- scratch (split re/im planes) ----------------
__device__ __align__(16) float g_Y [2u * 256 * 32768];   // [plane][h][pbc*32+y]
__device__ __align__(16) float g_Z [128u * 32768];       // [plane*64+j][pbc*32+y]
__device__ __align__(16) float g_Z3[128u * 32768];       // same layout
__device__ __align__(16) float g_V [262144u * 64];       // [(pbc*256+h)][plane*32+y]
__device__ __align__(16) float g_T1[256 * 64];           // [w][c]: c<32 cos, c>=32 -sin
__device__ __align__(16) float g_A2[128 * 512];          // fwd-H complex->real block matrix
__device__ __align__(16) float g_A4[512 * 128];          // inv-H complex->real block matrix
__device__ __align__(16) float g_T5[64 * 256];           // [k|32+k][w]: c_k cos /65536, -c_k sin /65536

// ---------------- table init ----------------
__global__ void init_tables() {
    int t = blockIdx.x * 256 + threadIdx.x;   // 0..65535
    if (t < 256 * 64) {
        int w = t >> 6, c = t & 63, y = c & 31;
        int m = (w * y) & 255;
        double s, ct; sincospi(2.0 * m / 256.0, &s, &ct);
        g_T1[t] = (c < 32) ? (float)ct : (float)(-s);
    }
    {
        int r = t >> 9, k = t & 511;
        int pk = k >> 8, h = k & 255;
        int j = r & 63;
        int xr = (j < 32) ? j : (192 + j);
        int m = (xr * h) & 255;
        double s, ct; sincospi(2.0 * m / 256.0, &s, &ct);
        float v;
        if (r < 64) v = (pk == 0) ? (float)ct : (float)s;
        else        v = (pk == 0) ? (float)(-s) : (float)ct;
        g_A2[t] = v;
    }
    {
        int r = t >> 7, c = t & 127;
        int pr = r >> 8, h = r & 255;
        int pc = c >> 6, j = c & 63;
        int xr = (j < 32) ? j : (192 + j);
        int m = (xr * h) & 255;
        double s, ct; sincospi(2.0 * m / 256.0, &s, &ct);
        float v;
        if (pr == 0) v = (pc == 0) ? (float)ct : (float)(-s);
        else         v = (pc == 0) ? (float)s  : (float)ct;
        g_A4[t] = v;
    }
    if (t < 64 * 256) {
        int r = t >> 8, w = t & 255, k = r & 31;
        int m = (k * w) & 255;
        double s, ct; sincospi(2.0 * m / 256.0, &s, &ct);
        double coef = ((k == 0) ? 1.0 : 2.0) / 65536.0;
        g_T5[t] = (r < 32) ? (float)(coef * ct) : (float)(-coef * s);
    }
}

// ---------------- templated SGEMM with packed f32x2 FMA ----------------
// C = A(MxK) * B(KxN), row-major. 256 threads, 8x8 microtile held as 8x4 f32x2 pairs.
// MODE 0: plain row-major C
// MODE 1: S1 epilogue -> Y planes  [plane][h][pbc*32+y]
// MODE 2: S4 epilogue -> V         [(pbc*256+h)][plane*32+y]
template<int BM, int BN, int BK, int TM, int TN, long M, long N, long K, int MODE>
__global__ void __launch_bounds__(256) sgemm(const float* __restrict__ A,
                                             const float* __restrict__ B,
                                             float* __restrict__ C) {
    constexpr int TX = BN / TN;
    constexpr int TY = BM / TM;
    static_assert(TX * TY == 256, "thread layout");
    constexpr int AF = BM * BK / 1024;   // float4s per thread for A tile
    constexpr int BF = BN * BK / 1024;
    __shared__ float As[BK][BM + 4];
    __shared__ float Bs[BK][BN];

    const int t = threadIdx.x;
    const int tx = t % TX, ty = t / TX;
    const long rowBase = (long)blockIdx.x * BM;
    const long colBase = (long)blockIdx.y * BN;

    float4 aReg[AF], bReg[BF];
    ull acc2[TM][TN / 2];
#pragma unroll
    for (int i = 0; i < TM; ++i)
#pragma unroll
        for (int j = 0; j < TN / 2; ++j) acc2[i][j] = 0ull;

    auto loadG = [&](long k0) {
#pragma unroll
        for (int f4 = 0; f4 < AF; ++f4) {
            int f = t + f4 * 256;
            int ar = f / (BK / 4), ac = f % (BK / 4);
            aReg[f4] = *reinterpret_cast<const float4*>(&A[(rowBase + ar) * K + k0 + ac * 4]);
        }
#pragma unroll
        for (int f4 = 0; f4 < BF; ++f4) {
            int f = t + f4 * 256;
            int br = f / (BN / 4), bc = f % (BN / 4);
            bReg[f4] = *reinterpret_cast<const float4*>(&B[(k0 + br) * N + colBase + bc * 4]);
        }
    };
    auto storeS = [&]() {
#pragma unroll
        for (int f4 = 0; f4 < AF; ++f4) {
            int f = t + f4 * 256;
            int ar = f / (BK / 4), ac = f % (BK / 4);
            As[ac * 4 + 0][ar] = aReg[f4].x;
            As[ac * 4 + 1][ar] = aReg[f4].y;
            As[ac * 4 + 2][ar] = aReg[f4].z;
            As[ac * 4 + 3][ar] = aReg[f4].w;
        }
#pragma unroll
        for (int f4 = 0; f4 < BF; ++f4) {
            int f = t + f4 * 256;
            int br = f / (BN / 4), bc = f % (BN / 4);
            *reinterpret_cast<float4*>(&Bs[br][bc * 4]) = bReg[f4];
        }
    };
    auto compute = [&]() {
#pragma unroll
        for (int kk = 0; kk < BK; ++kk) {
            float a[TM];
            ull a2[TM], b2[TN / 2];
#pragma unroll
            for (int q = 0; q < TM; q += 4)
                *reinterpret_cast<float4*>(&a[q]) =
                    *reinterpret_cast<const float4*>(&As[kk][ty * TM + q]);
#pragma unroll
            for (int q = 0; q < TN / 2; q += 2) {
                ulonglong2 bv = *reinterpret_cast<const ulonglong2*>(&Bs[kk][tx * TN + q * 2]);
                b2[q] = bv.x;
                b2[q + 1] = bv.y;
            }
#pragma unroll
            for (int i = 0; i < TM; ++i) a2[i] = dup2(a[i]);
#pragma unroll
            for (int i = 0; i < TM; ++i)
#pragma unroll
                for (int j = 0; j < TN / 2; ++j) ffma2(acc2[i][j], a2[i], b2[j]);
        }
    };

    loadG(0);
    storeS();
    __syncthreads();
    constexpr long KT = K / BK;
#pragma unroll 1
    for (long kt = 1; kt < KT; ++kt) {
        loadG(kt * BK);       // prefetch next tile into registers
        compute();            // compute on current smem tile
        __syncthreads();
        storeS();
        __syncthreads();
    }
    compute();

    // epilogue
#pragma unroll
    for (int i = 0; i < TM; ++i) {
        long r = rowBase + ty * TM + i;
#pragma unroll
        for (int jj = 0; jj < TN; jj += 4) {
            long c = colBase + tx * TN + jj;
            float2 p0 = unp2(acc2[i][jj / 2]);
            float2 p1 = unp2(acc2[i][jj / 2 + 1]);
            float4 v = make_float4(p0.x, p0.y, p1.x, p1.y);
            long addr;
            if (MODE == 0) {
                addr = r * N + c;
            } else if (MODE == 1) {
                long plane = c >> 5, y = c & 31;
                addr = plane * 8388608L + (r & 255) * 32768L + (r >> 8) * 32 + y;
            } else {
                long plane = r >> 8, h = r & 255, pbc = c >> 5, y = c & 31;
                addr = (pbc * 256 + h) * 64 + plane * 32 + y;
            }
            *reinterpret_cast<float4*>(&C[addr]) = v;
        }
    }
}

// ---------------- channel mix (plane layout) ----------------
__global__ void __launch_bounds__(256) chanmix(const float* __restrict__ Z,
                                               const float* __restrict__ w1re,
                                               const float* __restrict__ w1im,
                                               const float* __restrict__ w4re,
                                               const float* __restrict__ w4im,
                                               float* __restrict__ Z3) {
    __shared__ float Zs[2][4][32][32];   // plane, b, i, y   (32KB)
    __shared__ float Ws[2][2][32][32];   // o_half, plane, i, y (16KB)
    const int t = threadIdx.x;
    const int p = blockIdx.x >> 6;
    const int j = blockIdx.x & 63;
    const int x = j & 31;
    const float* wre = (j < 32) ? w1re : w4re;
    const float* wim = (j < 32) ? w1im : w4im;

#pragma unroll
    for (int pass = 0; pass < 8; ++pass) {
        int f = t + pass * 256;
        int plane = f >> 10;
        int rem = f & 1023;
        int bi = rem >> 3;
        int y4 = rem & 7;
        float4 v = *reinterpret_cast<const float4*>(
            &Z[(size_t)(plane * 64 + j) * 32768 + (size_t)(p * 128 + bi) * 32 + y4 * 4]);
        *reinterpret_cast<float4*>(&Zs[plane][bi >> 5][bi & 31][y4 * 4]) = v;
    }
    __syncthreads();

    const int o_l = t >> 7;
    const int bb  = (t >> 5) & 3;
    const int y   = t & 31;

    for (int o0 = 0; o0 < 32; o0 += 2) {
#pragma unroll
        for (int pass = 0; pass < 4; ++pass) {
            int f = t + pass * 256;
            int ol = f >> 9;
            int plane = (f >> 8) & 1;
            int i = (f >> 3) & 31;
            int y4 = f & 7;
            const float* wp = plane ? wim : wre;
            float4 v = *reinterpret_cast<const float4*>(
                &wp[((((size_t)(i * 32 + o0 + ol)) * 8 + p) * 32 + x) * 32 + y4 * 4]);
            *reinterpret_cast<float4*>(&Ws[ol][plane][i][y4 * 4]) = v;
        }
        __syncthreads();
        float accre = 0.f, accim = 0.f;
#pragma unroll
        for (int i = 0; i < 32; ++i) {
            float zre = Zs[0][bb][i][y], zim = Zs[1][bb][i][y];
            float wr  = Ws[o_l][0][i][y], wi = Ws[o_l][1][i][y];
            accre += zre * wr - zim * wi;
            accim += zre * wi + zim * wr;
        }
        int o = o0 + o_l;
        size_t col = (size_t)(p * 128 + bb * 32 + o) * 32 + y;
        Z3[(size_t)j * 32768 + col]          = accre;
        Z3[(size_t)(64 + j) * 32768 + col]   = accim;
        __syncthreads();
    }
}

// ---------------- launch ----------------
extern "C" void kernel_launch(void* const* d_in, const int* in_sizes, int n_in,
                              void* d_out, int out_size) {
    const float* x    = (const float*)d_in[0];
    const float* w1re = (const float*)d_in[1];
    const float* w1im = (const float*)d_in[2];
    const float* w4re = (const float*)d_in[3];
    const float* w4im = (const float*)d_in[4];
    float* out = (float*)d_out;

    void *pY, *pZ, *pZ3, *pV, *pT1, *pA2, *pA4, *pT5;
    cudaGetSymbolAddress(&pY,  g_Y);
    cudaGetSymbolAddress(&pZ,  g_Z);
    cudaGetSymbolAddress(&pZ3, g_Z3);
    cudaGetSymbolAddress(&pV,  g_V);
    cudaGetSymbolAddress(&pT1, g_T1);
    cudaGetSymbolAddress(&pA2, g_A2);
    cudaGetSymbolAddress(&pA4, g_A4);
    cudaGetSymbolAddress(&pT5, g_T5);

    init_tables<<<256, 256>>>();

    // S1: fwd W DFT -> Y planes.  (262144 x 64) = x(262144 x 256) * T1(256 x 64)
    sgemm<256, 64, 16, 8, 8, 262144L, 64L, 256L, 1>
        <<<dim3(1024, 1), 256>>>(x, (const float*)pT1, (float*)pY);

    // S2: fwd H DFT.  Z(128 x 32768) = A2(128 x 512) * Y(512 x 32768)
    sgemm<128, 128, 16, 8, 8, 128L, 32768L, 512L, 0>
        <<<dim3(1, 256), 256>>>((const float*)pA2, (const float*)pY, (float*)pZ);

    // S3: channel mixing
    chanmix<<<512, 256>>>((const float*)pZ, w1re, w1im, w4re, w4im, (float*)pZ3);

    // S4: inv H DFT -> V.  (512 x 32768) = A4(512 x 128) * Z3(128 x 32768)
    sgemm<128, 128, 16, 8, 8, 512L, 32768L, 128L, 2>
        <<<dim3(4, 256), 256>>>((const float*)pA4, (const float*)pZ3, (float*)pV);

    // S5: inv W DFT.  out(262144 x 256) = V(262144 x 64) * T5(64 x 256)
    sgemm<128, 128, 16, 8, 8, 262144L, 256L, 64L, 0>
        <<<dim3(2048, 2), 256>>>((const float*)pV, (const float*)pT5, out);
}

// round 5
// speedup vs baseline: 1.0800x; 1.0800x over previous
#include <cuda_runtime.h>
#include <cuda_bf16.h>
#include <cstdint>

// P=8, B=4, C=32, H=256, W=256, M1=M2=32
// rows R = P*B*C*H = 262144 ; pbc = P*B*C = 1024 ; cols (pbc,y) = 32768

typedef unsigned short ushort_t;

// ================= warp-MMA helpers (sm_80-era PTX: valid on compute_103) =================
__device__ __forceinline__ uint32_t smem_u32(const void* p) {
    uint32_t a;
    asm("{ .reg .u64 t; cvta.to.shared.u64 t, %1; cvt.u32.u64 %0, t; }" : "=r"(a) : "l"(p));
    return a;
}
__device__ __forceinline__ void ldm4(uint32_t* r, uint32_t a) {
    asm volatile("ldmatrix.sync.aligned.m8n8.x4.shared.b16 {%0,%1,%2,%3}, [%4];"
                 : "=r"(r[0]), "=r"(r[1]), "=r"(r[2]), "=r"(r[3]) : "r"(a));
}
__device__ __forceinline__ void ldm4t(uint32_t* r, uint32_t a) {
    asm volatile("ldmatrix.sync.aligned.m8n8.x4.trans.shared.b16 {%0,%1,%2,%3}, [%4];"
                 : "=r"(r[0]), "=r"(r[1]), "=r"(r[2]), "=r"(r[3]) : "r"(a));
}
__device__ __forceinline__ void mma16816(float* c, const uint32_t* a, const uint32_t* b) {
    asm volatile("mma.sync.aligned.m16n8k16.row.col.f32.bf16.bf16.f32 "
                 "{%0,%1,%2,%3}, {%4,%5,%6,%7}, {%8,%9}, {%0,%1,%2,%3};"
                 : "+f"(c[0]), "+f"(c[1]), "+f"(c[2]), "+f"(c[3])
                 : "r"(a[0]), "r"(a[1]), "r"(a[2]), "r"(a[3]), "r"(b[0]), "r"(b[1]));
}
__device__ __forceinline__ void bsplit(float v, ushort_t& h, ushort_t& l) {
    __nv_bfloat16 bh = __float2bfloat16(v);
    __nv_bfloat16 bl = __float2bfloat16(v - __bfloat162float(bh));
    h = __bfloat16_as_ushort(bh);
    l = __bfloat16_as_ushort(bl);
}

// ================= scratch =================
__device__ __align__(16) float g_Y [2u * 256 * 32768];      // [plane][h][pbc*32+y]
__device__ __align__(16) float g_Z [128u * 32768];          // [plane*64+j][col]
__device__ __align__(16) float g_Z3[128u * 32768];
__device__ __align__(16) ushort_t g_Vh[262144u * 64];       // bf16 hi of V, row-major [row][64]
__device__ __align__(16) ushort_t g_Vl[262144u * 64];       // bf16 lo
__device__ __align__(16) float g_T1[256 * 64];              // [w(k)][c(n)]: n<32 cos, n>=32 -sin
__device__ __align__(16) float g_A2[128 * 512];
__device__ __align__(16) float g_A4[512 * 128];
__device__ __align__(16) float g_T5[64 * 256];              // [k|32+k][w]

// ================= table init =================
__global__ void init_tables() {
    int t = blockIdx.x * 256 + threadIdx.x;   // 0..65535
    if (t < 256 * 64) {
        int w = t >> 6, c = t & 63, y = c & 31;
        int m = (w * y) & 255;
        double s, ct; sincospi(2.0 * m / 256.0, &s, &ct);
        g_T1[t] = (c < 32) ? (float)ct : (float)(-s);
    }
    {
        int r = t >> 9, k = t & 511;
        int pk = k >> 8, h = k & 255;
        int j = r & 63;
        int xr = (j < 32) ? j : (192 + j);
        int m = (xr * h) & 255;
        double s, ct; sincospi(2.0 * m / 256.0, &s, &ct);
        float v;
        if (r < 64) v = (pk == 0) ? (float)ct : (float)s;
        else        v = (pk == 0) ? (float)(-s) : (float)ct;
        g_A2[t] = v;
    }
    {
        int r = t >> 7, c = t & 127;
        int pr = r >> 8, h = r & 255;
        int pc = c >> 6, j = c & 63;
        int xr = (j < 32) ? j : (192 + j);
        int m = (xr * h) & 255;
        double s, ct; sincospi(2.0 * m / 256.0, &s, &ct);
        float v;
        if (pr == 0) v = (pc == 0) ? (float)ct : (float)(-s);
        else         v = (pc == 0) ? (float)s  : (float)ct;
        g_A4[t] = v;
    }
    if (t < 64 * 256) {
        int r = t >> 8, w = t & 255, k = r & 31;
        int m = (k * w) & 255;
        double s, ct; sincospi(2.0 * m / 256.0, &s, &ct);
        double coef = ((k == 0) ? 1.0 : 2.0) / 65536.0;
        g_T5[t] = (r < 32) ? (float)(coef * ct) : (float)(-coef * s);
    }
}

// ================= S1: warp-MMA fwd-W DFT =================
// Y(262144 x 64) = x(262144 x 256) * T1(256 x 64), bf16 hi/lo (3-pass).
// smem: Ah[128][264], Al, Bh[256][72], Bl (halves). Stage reuse for epilogue.
#define S1_ASH 0
#define S1_ASL 67584
#define S1_BSH 135168
#define S1_BSL 172032
#define S1_SMEM 208896

__global__ void __launch_bounds__(256) s1_mma(const float* __restrict__ X,
                                              float* __restrict__ Y) {
    extern __shared__ char smem[];
    const uint32_t sb = smem_u32(smem);
    const int t = threadIdx.x, wid = t >> 5, lane = t & 31;
    const long rowBase = (long)blockIdx.x * 128;

    // fill B (T1 is already [k=256][n=64] row-major)
#pragma unroll 4
    for (int i = 0; i < 64; ++i) {
        int idx = t + i * 256;
        int k = idx >> 6, n = idx & 63;
        ushort_t h, l;
        bsplit(g_T1[idx], h, l);
        *(ushort_t*)(smem + S1_BSH + (k * 72 + n) * 2) = h;
        *(ushort_t*)(smem + S1_BSL + (k * 72 + n) * 2) = l;
    }
    // fill A (X tile 128 x 256 fp32 -> bf16 hi/lo)
#pragma unroll 4
    for (int i = 0; i < 32; ++i) {
        int idx = t + i * 256;
        int r = idx >> 6, c4 = idx & 63;
        float4 v = reinterpret_cast<const float4*>(X)[rowBase * 64 + idx];
        ushort_t h0, l0, h1, l1, h2, l2, h3, l3;
        bsplit(v.x, h0, l0); bsplit(v.y, h1, l1);
        bsplit(v.z, h2, l2); bsplit(v.w, h3, l3);
        uint32_t off = (uint32_t)(r * 264 + c4 * 4) * 2;
        *(uint2*)(smem + S1_ASH + off) =
            make_uint2(h0 | ((uint32_t)h1 << 16), h2 | ((uint32_t)h3 << 16));
        *(uint2*)(smem + S1_ASL + off) =
            make_uint2(l0 | ((uint32_t)l1 << 16), l2 | ((uint32_t)l3 << 16));
    }
    __syncthreads();

    const int wm = wid >> 1, wn = wid & 1;   // warp tile: rows wm*32, cols wn*32
    float acc[2][4][4];
#pragma unroll
    for (int a = 0; a < 2; ++a)
#pragma unroll
        for (int b = 0; b < 4; ++b)
#pragma unroll
            for (int q = 0; q < 4; ++q) acc[a][b][q] = 0.f;

#pragma unroll
    for (int ks = 0; ks < 16; ++ks) {
        const int k0 = ks * 16;
        uint32_t ah[2][4], al[2][4];
#pragma unroll
        for (int mt = 0; mt < 2; ++mt) {
            int row = wm * 32 + mt * 16 + (lane & 15);
            int col = k0 + ((lane >> 4) << 3);
            uint32_t off = (uint32_t)(row * 264 + col) * 2;
            ldm4(ah[mt], sb + S1_ASH + off);
            ldm4(al[mt], sb + S1_ASL + off);
        }
#pragma unroll
        for (int pr = 0; pr < 2; ++pr) {
            uint32_t bh[4], bl[4];
            int ntile = pr * 2 + (lane >> 4);
            int krow = k0 + ((lane >> 3) & 1) * 8 + (lane & 7);
            uint32_t boff = (uint32_t)(krow * 72 + wn * 32 + ntile * 8) * 2;
            ldm4t(bh, sb + S1_BSH + boff);
            ldm4t(bl, sb + S1_BSL + boff);
#pragma unroll
            for (int mt = 0; mt < 2; ++mt)
#pragma unroll
                for (int nn = 0; nn < 2; ++nn) {
                    float* c = acc[mt][pr * 2 + nn];
                    mma16816(c, ah[mt], bh + nn * 2);
                    mma16816(c, al[mt], bh + nn * 2);
                    mma16816(c, ah[mt], bl + nn * 2);
                }
        }
    }
    __syncthreads();

    // stage (128 x 68 f32, reuses A region) then coalesced plane writes
    float* stage = reinterpret_cast<float*>(smem);
    const int g = lane >> 2, tq = lane & 3;
#pragma unroll
    for (int mt = 0; mt < 2; ++mt)
#pragma unroll
        for (int nt = 0; nt < 4; ++nt) {
            const float* c = acc[mt][nt];
            int row = wm * 32 + mt * 16 + g;
            int col = wn * 32 + nt * 8 + tq * 2;
            *(float2*)&stage[row * 68 + col]       = make_float2(c[0], c[1]);
            *(float2*)&stage[(row + 8) * 68 + col] = make_float2(c[2], c[3]);
        }
    __syncthreads();
    const long pbc = rowBase >> 8;
    const int hb = (int)(rowBase & 255);
#pragma unroll
    for (int i = 0; i < 8; ++i) {
        int idx = t + i * 256;
        int r = idx >> 4, c4 = idx & 15;
        int c = c4 * 4, plane = c >> 5, y = c & 31;
        float4 v = *(float4*)&stage[r * 68 + c];
        *(float4*)&Y[(long)plane * 8388608L + (long)(hb + r) * 32768L + pbc * 32 + y] = v;
    }
}

// ================= S5: warp-MMA inv-W DFT =================
// out(262144 x 256) = V(262144 x 64) * T5(64 x 256), V pre-split bf16 hi/lo.
#define S5_ASH 0
#define S5_ASL 18432
#define S5_BSH 36864
#define S5_BSL 70656
#define S5_SMEM 104448

__global__ void __launch_bounds__(256) s5_mma(const ushort_t* __restrict__ Vh,
                                              const ushort_t* __restrict__ Vl,
                                              float* __restrict__ out) {
    extern __shared__ char smem[];
    const uint32_t sb = smem_u32(smem);
    const int t = threadIdx.x, wid = t >> 5, lane = t & 31;
    const long rowBase = (long)blockIdx.x * 128;

    // fill A (V tile 128 x 64 halves per plane)
    const uint2* vh2 = reinterpret_cast<const uint2*>(Vh);
    const uint2* vl2 = reinterpret_cast<const uint2*>(Vl);
#pragma unroll
    for (int i = 0; i < 8; ++i) {
        int idx = t + i * 256;
        int r = idx >> 4, q = idx & 15;
        uint2 a = vh2[rowBase * 16 + idx];
        uint2 b = vl2[rowBase * 16 + idx];
        uint32_t off = (uint32_t)(r * 72 + q * 4) * 2;
        *(uint2*)(smem + S5_ASH + off) = a;
        *(uint2*)(smem + S5_ASL + off) = b;
    }
    // fill B (T5 is [k=64][n=256] row-major)
#pragma unroll 4
    for (int i = 0; i < 64; ++i) {
        int idx = t + i * 256;
        int k = idx >> 8, n = idx & 255;
        ushort_t h, l;
        bsplit(g_T5[idx], h, l);
        *(ushort_t*)(smem + S5_BSH + (k * 264 + n) * 2) = h;
        *(ushort_t*)(smem + S5_BSL + (k * 264 + n) * 2) = l;
    }
    __syncthreads();

    const int wm = wid >> 2, wn = wid & 3;   // warp tile: rows wm*64, cols wn*64
    float acc[4][8][4];
#pragma unroll
    for (int a = 0; a < 4; ++a)
#pragma unroll
        for (int b = 0; b < 8; ++b)
#pragma unroll
            for (int q = 0; q < 4; ++q) acc[a][b][q] = 0.f;

#pragma unroll
    for (int ks = 0; ks < 4; ++ks) {
        const int k0 = ks * 16;
        uint32_t ah[4][4], al[4][4];
#pragma unroll
        for (int mt = 0; mt < 4; ++mt) {
            int row = wm * 64 + mt * 16 + (lane & 15);
            int col = k0 + ((lane >> 4) << 3);
            uint32_t off = (uint32_t)(row * 72 + col) * 2;
            ldm4(ah[mt], sb + S5_ASH + off);
            ldm4(al[mt], sb + S5_ASL + off);
        }
#pragma unroll
        for (int pr = 0; pr < 4; ++pr) {
            uint32_t bh[4], bl[4];
            int ntile = pr * 2 + (lane >> 4);
            int krow = k0 + ((lane >> 3) & 1) * 8 + (lane & 7);
            uint32_t boff = (uint32_t)(krow * 264 + wn * 64 + ntile * 8) * 2;
            ldm4t(bh, sb + S5_BSH + boff);
            ldm4t(bl, sb + S5_BSL + boff);
#pragma unroll
            for (int mt = 0; mt < 4; ++mt)
#pragma unroll
                for (int nn = 0; nn < 2; ++nn) {
                    float* c = acc[mt][pr * 2 + nn];
                    mma16816(c, ah[mt], bh + nn * 2);
                    mma16816(c, al[mt], bh + nn * 2);
                    mma16816(c, ah[mt], bl + nn * 2);
                }
        }
    }

    // epilogue in two 64-row halves via smem stage (64 x 260 f32)
    float* stage = reinterpret_cast<float*>(smem);
    const int g = lane >> 2, tq = lane & 3;
#pragma unroll 1
    for (int hh = 0; hh < 2; ++hh) {
        __syncthreads();
        if (wm == hh) {
#pragma unroll
            for (int mt = 0; mt < 4; ++mt)
#pragma unroll
                for (int nt = 0; nt < 8; ++nt) {
                    const float* c = acc[mt][nt];
                    int row = mt * 16 + g;
                    int col = wn * 64 + nt * 8 + tq * 2;
                    *(float2*)&stage[row * 260 + col]       = make_float2(c[0], c[1]);
                    *(float2*)&stage[(row + 8) * 260 + col] = make_float2(c[2], c[3]);
                }
        }
        __syncthreads();
#pragma unroll
        for (int i = 0; i < 16; ++i) {
            int idx = t + i * 256;
            int r = idx >> 6, c4 = idx & 63;
            float4 v = *(float4*)&stage[r * 260 + c4 * 4];
            *(float4*)&out[(rowBase + hh * 64 + r) * 256 + c4 * 4] = v;
        }
    }
}

// ================= scalar SGEMM (S2 / S4) =================
// MODE 0: plain row-major C.  MODE 2: S4 epilogue -> V bf16 hi/lo [(pbc*256+h)][plane*32+y]
template<int BM, int BN, int BK, int TM, int TN, long M, long N, long K, int MODE>
__global__ void __launch_bounds__(256) sgemm(const float* __restrict__ A,
                                             const float* __restrict__ B,
                                             float* __restrict__ C) {
    constexpr int TX = BN / TN;
    constexpr int TY = BM / TM;
    static_assert(TX * TY == 256, "thread layout");
    constexpr int AF = BM * BK / 1024;
    constexpr int BF = BN * BK / 1024;
    __shared__ float As[BK][BM + 4];
    __shared__ float Bs[BK][BN];

    const int t = threadIdx.x;
    const int tx = t % TX, ty = t / TX;
    const long rowBase = (long)blockIdx.x * BM;
    const long colBase = (long)blockIdx.y * BN;

    float4 aReg[AF], bReg[BF];
    float acc[TM][TN];
#pragma unroll
    for (int i = 0; i < TM; ++i)
#pragma unroll
        for (int j = 0; j < TN; ++j) acc[i][j] = 0.f;

    auto loadG = [&](long k0) {
#pragma unroll
        for (int f4 = 0; f4 < AF; ++f4) {
            int f = t + f4 * 256;
            int ar = f / (BK / 4), ac = f % (BK / 4);
            aReg[f4] = *reinterpret_cast<const float4*>(&A[(rowBase + ar) * K + k0 + ac * 4]);
        }
#pragma unroll
        for (int f4 = 0; f4 < BF; ++f4) {
            int f = t + f4 * 256;
            int br = f / (BN / 4), bc = f % (BN / 4);
            bReg[f4] = *reinterpret_cast<const float4*>(&B[(k0 + br) * N + colBase + bc * 4]);
        }
    };
    auto storeS = [&]() {
#pragma unroll
        for (int f4 = 0; f4 < AF; ++f4) {
            int f = t + f4 * 256;
            int ar = f / (BK / 4), ac = f % (BK / 4);
            As[ac * 4 + 0][ar] = aReg[f4].x;
            As[ac * 4 + 1][ar] = aReg[f4].y;
            As[ac * 4 + 2][ar] = aReg[f4].z;
            As[ac * 4 + 3][ar] = aReg[f4].w;
        }
#pragma unroll
        for (int f4 = 0; f4 < BF; ++f4) {
            int f = t + f4 * 256;
            int br = f / (BN / 4), bc = f % (BN / 4);
            *reinterpret_cast<float4*>(&Bs[br][bc * 4]) = bReg[f4];
        }
    };
    auto compute = [&]() {
#pragma unroll
        for (int kk = 0; kk < BK; ++kk) {
            float a[TM], b[TN];
#pragma unroll
            for (int q = 0; q < TM; q += 4)
                *reinterpret_cast<float4*>(&a[q]) =
                    *reinterpret_cast<const float4*>(&As[kk][ty * TM + q]);
#pragma unroll
            for (int q = 0; q < TN; q += 4)
                *reinterpret_cast<float4*>(&b[q]) =
                    *reinterpret_cast<const float4*>(&Bs[kk][tx * TN + q]);
#pragma unroll
            for (int i = 0; i < TM; ++i)
#pragma unroll
                for (int j = 0; j < TN; ++j) acc[i][j] += a[i] * b[j];
        }
    };

    loadG(0);
    storeS();
    __syncthreads();
    constexpr long KT = K / BK;
#pragma unroll 1
    for (long kt = 1; kt < KT; ++kt) {
        loadG(kt * BK);
        compute();
        __syncthreads();
        storeS();
        __syncthreads();
    }
    compute();

#pragma unroll
    for (int i = 0; i < TM; ++i) {
        long r = rowBase + ty * TM + i;
#pragma unroll
        for (int jj = 0; jj < TN; jj += 4) {
            long c = colBase + tx * TN + jj;
            float4 v = make_float4(acc[i][jj], acc[i][jj + 1], acc[i][jj + 2], acc[i][jj + 3]);
            if (MODE == 0) {
                *reinterpret_cast<float4*>(&C[r * N + c]) = v;
            } else {
                long plane = r >> 8, h = r & 255, pbc = c >> 5, y = c & 31;
                long addr = (pbc * 256 + h) * 64 + plane * 32 + y;
                float f[4] = {v.x, v.y, v.z, v.w};
                ushort_t hs[4], ls[4];
#pragma unroll
                for (int q = 0; q < 4; ++q) bsplit(f[q], hs[q], ls[q]);
                *reinterpret_cast<uint2*>(&g_Vh[addr]) =
                    make_uint2(hs[0] | ((uint32_t)hs[1] << 16), hs[2] | ((uint32_t)hs[3] << 16));
                *reinterpret_cast<uint2*>(&g_Vl[addr]) =
                    make_uint2(ls[0] | ((uint32_t)ls[1] << 16), ls[2] | ((uint32_t)ls[3] << 16));
            }
        }
    }
}

// ================= channel mix (unchanged) =================
__global__ void __launch_bounds__(256) chanmix(const float* __restrict__ Z,
                                               const float* __restrict__ w1re,
                                               const float* __restrict__ w1im,
                                               const float* __restrict__ w4re,
                                               const float* __restrict__ w4im,
                                               float* __restrict__ Z3) {
    __shared__ float Zs[2][4][32][32];
    __shared__ float Ws[2][2][32][32];
    const int t = threadIdx.x;
    const int p = blockIdx.x >> 6;
    const int j = blockIdx.x & 63;
    const int x = j & 31;
    const float* wre = (j < 32) ? w1re : w4re;
    const float* wim = (j < 32) ? w1im : w4im;

#pragma unroll
    for (int pass = 0; pass < 8; ++pass) {
        int f = t + pass * 256;
        int plane = f >> 10;
        int rem = f & 1023;
        int bi = rem >> 3;
        int y4 = rem & 7;
        float4 v = *reinterpret_cast<const float4*>(
            &Z[(size_t)(plane * 64 + j) * 32768 + (size_t)(p * 128 + bi) * 32 + y4 * 4]);
        *reinterpret_cast<float4*>(&Zs[plane][bi >> 5][bi & 31][y4 * 4]) = v;
    }
    __syncthreads();

    const int o_l = t >> 7;
    const int bb  = (t >> 5) & 3;
    const int y   = t & 31;

    for (int o0 = 0; o0 < 32; o0 += 2) {
#pragma unroll
        for (int pass = 0; pass < 4; ++pass) {
            int f = t + pass * 256;
            int ol = f >> 9;
            int plane = (f >> 8) & 1;
            int i = (f >> 3) & 31;
            int y4 = f & 7;
            const float* wp = plane ? wim : wre;
            float4 v = *reinterpret_cast<const float4*>(
                &wp[((((size_t)(i * 32 + o0 + ol)) * 8 + p) * 32 + x) * 32 + y4 * 4]);
            *reinterpret_cast<float4*>(&Ws[ol][plane][i][y4 * 4]) = v;
        }
        __syncthreads();
        float accre = 0.f, accim = 0.f;
#pragma unroll
        for (int i = 0; i < 32; ++i) {
            float zre = Zs[0][bb][i][y], zim = Zs[1][bb][i][y];
            float wr  = Ws[o_l][0][i][y], wi = Ws[o_l][1][i][y];
            accre += zre * wr - zim * wi;
            accim += zre * wi + zim * wr;
        }
        int o = o0 + o_l;
        size_t col = (size_t)(p * 128 + bb * 32 + o) * 32 + y;
        Z3[(size_t)j * 32768 + col]        = accre;
        Z3[(size_t)(64 + j) * 32768 + col] = accim;
        __syncthreads();
    }
}

// ================= launch =================
extern "C" void kernel_launch(void* const* d_in, const int* in_sizes, int n_in,
                              void* d_out, int out_size) {
    const float* x    = (const float*)d_in[0];
    const float* w1re = (const float*)d_in[1];
    const float* w1im = (const float*)d_in[2];
    const float* w4re = (const float*)d_in[3];
    const float* w4im = (const float*)d_in[4];
    float* out = (float*)d_out;

    void *pY, *pZ, *pZ3, *pVh, *pVl, *pA2, *pA4;
    cudaGetSymbolAddress(&pY,  g_Y);
    cudaGetSymbolAddress(&pZ,  g_Z);
    cudaGetSymbolAddress(&pZ3, g_Z3);
    cudaGetSymbolAddress(&pVh, g_Vh);
    cudaGetSymbolAddress(&pVl, g_Vl);
    cudaGetSymbolAddress(&pA2, g_A2);
    cudaGetSymbolAddress(&pA4, g_A4);

    cudaFuncSetAttribute(s1_mma, cudaFuncAttributeMaxDynamicSharedMemorySize, S1_SMEM);
    cudaFuncSetAttribute(s5_mma, cudaFuncAttributeMaxDynamicSharedMemorySize, S5_SMEM);

    init_tables<<<256, 256>>>();

    // S1: fwd W DFT (tensor via mma.sync)
    s1_mma<<<2048, 256, S1_SMEM>>>(x, (float*)pY);

    // S2: fwd H DFT.  Z(128 x 32768) = A2(128 x 512) * Y(512 x 32768)
    sgemm<128, 128, 16, 8, 8, 128L, 32768L, 512L, 0>
        <<<dim3(1, 256), 256>>>((const float*)pA2, (const float*)pY, (float*)pZ);

    // S3: channel mixing
    chanmix<<<512, 256>>>((const float*)pZ, w1re, w1im, w4re, w4im, (float*)pZ3);

    // S4: inv H DFT -> V bf16 hi/lo.  (512 x 32768) = A4(512 x 128) * Z3(128 x 32768)
    sgemm<128, 128, 16, 8, 8, 512L, 32768L, 128L, 2>
        <<<dim3(4, 256), 256>>>((const float*)pA4, (const float*)pZ3, (float*)pVh);

    // S5: inv W DFT (tensor via mma.sync)
    s5_mma<<<2048, 256, S5_SMEM>>>((const ushort_t*)pVh, (const ushort_t*)pVl, out);
}

// round 7
// speedup vs baseline: 1.6930x; 1.5676x over previous
#include <cuda_runtime.h>
#include <cuda_bf16.h>
#include <cstdint>

// P=8, B=4, C=32, H=256, W=256, M1=M2=32
// rows R = P*B*C*H = 262144 ; pbc = P*B*C = 1024 ; cols (pbc,y) = 32768

typedef unsigned short ushort_t;

// ================= helpers =================
__device__ __forceinline__ uint32_t smem_u32(const void* p) {
    uint32_t a;
    asm("{ .reg .u64 t; cvta.to.shared.u64 t, %1; cvt.u32.u64 %0, t; }" : "=r"(a) : "l"(p));
    return a;
}
__device__ __forceinline__ void ldm4(uint32_t* r, uint32_t a) {
    asm volatile("ldmatrix.sync.aligned.m8n8.x4.shared.b16 {%0,%1,%2,%3}, [%4];"
                 : "=r"(r[0]), "=r"(r[1]), "=r"(r[2]), "=r"(r[3]) : "r"(a));
}
__device__ __forceinline__ void ldm4t(uint32_t* r, uint32_t a) {
    asm volatile("ldmatrix.sync.aligned.m8n8.x4.trans.shared.b16 {%0,%1,%2,%3}, [%4];"
                 : "=r"(r[0]), "=r"(r[1]), "=r"(r[2]), "=r"(r[3]) : "r"(a));
}
__device__ __forceinline__ void mma16816(float* c, const uint32_t* a, const uint32_t* b) {
    asm volatile("mma.sync.aligned.m16n8k16.row.col.f32.bf16.bf16.f32 "
                 "{%0,%1,%2,%3}, {%4,%5,%6,%7}, {%8,%9}, {%0,%1,%2,%3};"
                 : "+f"(c[0]), "+f"(c[1]), "+f"(c[2]), "+f"(c[3])
                 : "r"(a[0]), "r"(a[1]), "r"(a[2]), "r"(a[3]), "r"(b[0]), "r"(b[1]));
}
__device__ __forceinline__ void bsplit(float v, ushort_t& h, ushort_t& l) {
    __nv_bfloat16 bh = __float2bfloat16(v);
    __nv_bfloat16 bl = __float2bfloat16(v - __bfloat162float(bh));
    h = __bfloat16_as_ushort(bh);
    l = __bfloat16_as_ushort(bl);
}

// ================= scratch =================
__device__ __align__(16) float g_Y [2u * 256 * 32768];      // [plane][h][pbc*32+y]
__device__ __align__(16) float g_Z [128u * 32768];          // [plane*64+j][col]
__device__ __align__(16) float g_Z3[128u * 32768];
__device__ __align__(16) ushort_t g_Vh[262144u * 64];       // bf16 hi of V, row-major [row][64]
__device__ __align__(16) ushort_t g_Vl[262144u * 64];       // bf16 lo
__device__ __align__(16) float g_T1[256 * 64];              // [w(k)][c(n)]
__device__ __align__(16) float g_A2[128 * 512];
__device__ __align__(16) float g_A4[512 * 128];
__device__ __align__(16) float g_T5[64 * 256];              // [k][w]

// ================= table init =================
__global__ void init_tables() {
    int t = blockIdx.x * 256 + threadIdx.x;   // 0..65535
    if (t < 256 * 64) {
        int w = t >> 6, c = t & 63, y = c & 31;
        int m = (w * y) & 255;
        double s, ct; sincospi(2.0 * m / 256.0, &s, &ct);
        g_T1[t] = (c < 32) ? (float)ct : (float)(-s);
    }
    {
        int r = t >> 9, k = t & 511;
        int pk = k >> 8, h = k & 255;
        int j = r & 63;
        int xr = (j < 32) ? j : (192 + j);
        int m = (xr * h) & 255;
        double s, ct; sincospi(2.0 * m / 256.0, &s, &ct);
        float v;
        if (r < 64) v = (pk == 0) ? (float)ct : (float)s;
        else        v = (pk == 0) ? (float)(-s) : (float)ct;
        g_A2[t] = v;
    }
    {
        int r = t >> 7, c = t & 127;
        int pr = r >> 8, h = r & 255;
        int pc = c >> 6, j = c & 63;
        int xr = (j < 32) ? j : (192 + j);
        int m = (xr * h) & 255;
        double s, ct; sincospi(2.0 * m / 256.0, &s, &ct);
        float v;
        if (pr == 0) v = (pc == 0) ? (float)ct : (float)(-s);
        else         v = (pc == 0) ? (float)s  : (float)ct;
        g_A4[t] = v;
    }
    if (t < 64 * 256) {
        int r = t >> 8, w = t & 255, k = r & 31;
        int m = (k * w) & 255;
        double s, ct; sincospi(2.0 * m / 256.0, &s, &ct);
        double coef = ((k == 0) ? 1.0 : 2.0) / 65536.0;
        g_T5[t] = (r < 32) ? (float)(coef * ct) : (float)(-coef * s);
    }
}

// ================= unified pipelined warp-MMA GEMM =================
// C(M x NTOT) = A(M x KDIM) * B(KDIM x NTOT), bf16 hi/lo 3-pass.
// AMODE 0: A fp32 (convert+split).  AMODE 1: A pre-split (Ahg/Alg, row stride KDIM).
// CMODE 0: row-major f32 C.
// CMODE 1: S1 plane scatter -> Y[plane][h][pbc*32+y] (staged).
// CMODE 2: S4 emit -> g_Vh/g_Vl [(pbc*256+h)][plane*32+y].
// CMODE 3: row-major f32 C via coalescing stage.
template<int BM, int BN, int BK, int WM, int WN, long KDIM, long NTOT, int AMODE, int CMODE>
__global__ void __launch_bounds__(256, 2) mgemm(
    const float* __restrict__ Af, const ushort_t* __restrict__ Ahg,
    const ushort_t* __restrict__ Alg, const float* __restrict__ Bf,
    float* __restrict__ Cf)
{
    constexpr int TWM = BM / WM, TWN = BN / WN, MT = TWM / 16, NT = TWN / 8;
    constexpr int BKP = BK + 8, BNP = BN + 8;
    constexpr int PA = BM * BKP * 2;            // bytes per A plane
    constexpr int PB = BK * BNP * 2;            // bytes per B plane
    constexpr int OAH = 0, OAL = PA, OBH = 2 * PA, OBL = 2 * PA + PB;
    constexpr int AF4 = BM * BK / 1024, BF4 = BK * BN / 1024;
    constexpr long KT = KDIM / BK;
    static_assert(WM * WN == 8 && (NT % 2) == 0, "cfg");

    extern __shared__ char smem[];
    const uint32_t sb = smem_u32(smem);
    const int t = threadIdx.x, wid = t >> 5, lane = t & 31;
    const int wm = wid / WN, wn = wid % WN;
    const long rowBase = (long)blockIdx.x * BM;
    const long colBase = (long)blockIdx.y * BN;

    float4 aReg[AF4];
    uint2  ahReg[AF4], alReg[AF4];
    float4 bReg[BF4];
    float  acc[MT][NT][4];
#pragma unroll
    for (int i = 0; i < MT; ++i)
#pragma unroll
        for (int j = 0; j < NT; ++j)
#pragma unroll
            for (int q = 0; q < 4; ++q) acc[i][j][q] = 0.f;

    auto loadG = [&](long k0) {
        if constexpr (AMODE == 0) {
#pragma unroll
            for (int f4 = 0; f4 < AF4; ++f4) {
                int f = t + f4 * 256;
                int ar = f / (BK / 4), ac = f % (BK / 4);
                aReg[f4] = *reinterpret_cast<const float4*>(
                    &Af[(rowBase + ar) * KDIM + k0 + ac * 4]);
            }
        } else {
#pragma unroll
            for (int f4 = 0; f4 < AF4; ++f4) {
                int f = t + f4 * 256;
                int ar = f / (BK / 4), q = f % (BK / 4);
                ahReg[f4] = reinterpret_cast<const uint2*>(Ahg)[(rowBase + ar) * (BK / 4) + q];
                alReg[f4] = reinterpret_cast<const uint2*>(Alg)[(rowBase + ar) * (BK / 4) + q];
            }
        }
#pragma unroll
        for (int f4 = 0; f4 < BF4; ++f4) {
            int f = t + f4 * 256;
            int br = f / (BN / 4), bc = f % (BN / 4);
            bReg[f4] = *reinterpret_cast<const float4*>(
                &Bf[(k0 + br) * NTOT + colBase + bc * 4]);
        }
    };
    auto storeS = [&]() {
        if constexpr (AMODE == 0) {
#pragma unroll
            for (int f4 = 0; f4 < AF4; ++f4) {
                int f = t + f4 * 256;
                int ar = f / (BK / 4), ac = f % (BK / 4);
                float fv[4] = {aReg[f4].x, aReg[f4].y, aReg[f4].z, aReg[f4].w};
                ushort_t hs[4], ls[4];
#pragma unroll
                for (int q = 0; q < 4; ++q) bsplit(fv[q], hs[q], ls[q]);
                uint32_t off = (uint32_t)(ar * BKP + ac * 4) * 2;
                *reinterpret_cast<uint2*>(smem + OAH + off) =
                    make_uint2(hs[0] | ((uint32_t)hs[1] << 16), hs[2] | ((uint32_t)hs[3] << 16));
                *reinterpret_cast<uint2*>(smem + OAL + off) =
                    make_uint2(ls[0] | ((uint32_t)ls[1] << 16), ls[2] | ((uint32_t)ls[3] << 16));
            }
        } else {
#pragma unroll
            for (int f4 = 0; f4 < AF4; ++f4) {
                int f = t + f4 * 256;
                int ar = f / (BK / 4), q = f % (BK / 4);
                uint32_t off = (uint32_t)(ar * BKP + q * 4) * 2;
                *reinterpret_cast<uint2*>(smem + OAH + off) = ahReg[f4];
                *reinterpret_cast<uint2*>(smem + OAL + off) = alReg[f4];
            }
        }
#pragma unroll
        for (int f4 = 0; f4 < BF4; ++f4) {
            int f = t + f4 * 256;
            int br = f / (BN / 4), bc = f % (BN / 4);
            float fv[4] = {bReg[f4].x, bReg[f4].y, bReg[f4].z, bReg[f4].w};
            ushort_t hs[4], ls[4];
#pragma unroll
            for (int q = 0; q < 4; ++q) bsplit(fv[q], hs[q], ls[q]);
            uint32_t off = (uint32_t)(br * BNP + bc * 4) * 2;
            *reinterpret_cast<uint2*>(smem + OBH + off) =
                make_uint2(hs[0] | ((uint32_t)hs[1] << 16), hs[2] | ((uint32_t)hs[3] << 16));
            *reinterpret_cast<uint2*>(smem + OBL + off) =
                make_uint2(ls[0] | ((uint32_t)ls[1] << 16), ls[2] | ((uint32_t)ls[3] << 16));
        }
    };
    auto compute = [&]() {
#pragma unroll
        for (int ks = 0; ks < BK / 16; ++ks) {
            const int k0 = ks * 16;
            uint32_t ah[MT][4], al[MT][4];
#pragma unroll
            for (int i = 0; i < MT; ++i) {
                int row = wm * TWM + i * 16 + (lane & 15);
                int col = k0 + ((lane >> 4) << 3);
                uint32_t off = (uint32_t)(row * BKP + col) * 2;
                ldm4(ah[i], sb + OAH + off);
                ldm4(al[i], sb + OAL + off);
            }
#pragma unroll
            for (int pr = 0; pr < NT / 2; ++pr) {
                uint32_t bh[4], bl[4];
                int krow = k0 + ((lane >> 3) & 1) * 8 + (lane & 7);
                int coln = wn * TWN + (pr * 2 + (lane >> 4)) * 8;
                uint32_t boff = (uint32_t)(krow * BNP + coln) * 2;
                ldm4t(bh, sb + OBH + boff);
                ldm4t(bl, sb + OBL + boff);
#pragma unroll
                for (int i = 0; i < MT; ++i)
#pragma unroll
                    for (int nn = 0; nn < 2; ++nn) {
                        float* c = acc[i][pr * 2 + nn];
                        mma16816(c, ah[i], bh + nn * 2);
                        mma16816(c, al[i], bh + nn * 2);
                        mma16816(c, ah[i], bl + nn * 2);
                    }
            }
        }
    };

    loadG(0);
    storeS();
    __syncthreads();
#pragma unroll 1
    for (long kt = 1; kt < KT; ++kt) {
        loadG(kt * BK);
        compute();
        __syncthreads();
        storeS();
        __syncthreads();
    }
    compute();

    const int g = lane >> 2, tq = lane & 3;
    if constexpr (CMODE == 0) {
#pragma unroll
        for (int i = 0; i < MT; ++i)
#pragma unroll
            for (int j = 0; j < NT; ++j) {
                const float* c = acc[i][j];
                long r0 = rowBase + wm * TWM + i * 16 + g;
                long c0 = colBase + wn * TWN + j * 8 + tq * 2;
                *reinterpret_cast<float2*>(&Cf[r0 * NTOT + c0])       = make_float2(c[0], c[1]);
                *reinterpret_cast<float2*>(&Cf[(r0 + 8) * NTOT + c0]) = make_float2(c[2], c[3]);
            }
    } else if constexpr (CMODE == 2) {
#pragma unroll
        for (int i = 0; i < MT; ++i)
#pragma unroll
            for (int j = 0; j < NT; ++j) {
                const float* c = acc[i][j];
                long r0 = rowBase + wm * TWM + i * 16 + g;
                long c0 = colBase + wn * TWN + j * 8 + tq * 2;
                long pbc = c0 >> 5, y = c0 & 31;
#pragma unroll
                for (int rr = 0; rr < 2; ++rr) {
                    long r = r0 + rr * 8;
                    long plane = r >> 8, h = r & 255;
                    long addr = (pbc * 256 + h) * 64 + plane * 32 + y;
                    ushort_t h0, l0, h1, l1;
                    bsplit(c[rr * 2], h0, l0);
                    bsplit(c[rr * 2 + 1], h1, l1);
                    *reinterpret_cast<uint32_t*>(&g_Vh[addr]) = h0 | ((uint32_t)h1 << 16);
                    *reinterpret_cast<uint32_t*>(&g_Vl[addr]) = l0 | ((uint32_t)l1 << 16);
                }
            }
    } else {
        // staged row-major (CMODE 3) / plane scatter (CMODE 1)
        constexpr int STOFF = (CMODE == 3) ? OBH : 0;
        float* stage = reinterpret_cast<float*>(smem + STOFF);
        __syncthreads();
#pragma unroll
        for (int i = 0; i < MT; ++i)
#pragma unroll
            for (int j = 0; j < NT; ++j) {
                const float* c = acc[i][j];
                int row = wm * TWM + i * 16 + g;
                int col = wn * TWN + j * 8 + tq * 2;
                *reinterpret_cast<float2*>(&stage[row * (BN + 4) + col])       = make_float2(c[0], c[1]);
                *reinterpret_cast<float2*>(&stage[(row + 8) * (BN + 4) + col]) = make_float2(c[2], c[3]);
            }
        __syncthreads();
        if constexpr (CMODE == 1) {
            const long pbc = rowBase >> 8;
            const int hb = (int)(rowBase & 255);
#pragma unroll
            for (int it = 0; it < BM * BN / 1024; ++it) {
                int idx = t + it * 256;
                int r = idx / (BN / 4), c4 = idx % (BN / 4);
                float4 v = *reinterpret_cast<float4*>(&stage[r * (BN + 4) + c4 * 4]);
                int c = c4 * 4, plane = c >> 5, y = c & 31;
                *reinterpret_cast<float4*>(
                    &Cf[(long)plane * 8388608L + (long)(hb + r) * 32768L + pbc * 32 + y]) = v;
            }
        } else {
#pragma unroll
            for (int it = 0; it < BM * BN / 1024; ++it) {
                int idx = t + it * 256;
                int r = idx / (BN / 4), c4 = idx % (BN / 4);
                float4 v = *reinterpret_cast<float4*>(&stage[r * (BN + 4) + c4 * 4]);
                *reinterpret_cast<float4*>(&Cf[(rowBase + r) * NTOT + colBase + c4 * 4]) = v;
            }
        }
    }
}

// ================= channel mix (unchanged, known-good) =================
__global__ void __launch_bounds__(256) chanmix(const float* __restrict__ Z,
                                               const float* __restrict__ w1re,
                                               const float* __restrict__ w1im,
                                               const float* __restrict__ w4re,
                                               const float* __restrict__ w4im,
                                               float* __restrict__ Z3) {
    __shared__ float Zs[2][4][32][32];
    __shared__ float Ws[2][2][32][32];
    const int t = threadIdx.x;
    const int p = blockIdx.x >> 6;
    const int j = blockIdx.x & 63;
    const int x = j & 31;
    const float* wre = (j < 32) ? w1re : w4re;
    const float* wim = (j < 32) ? w1im : w4im;

#pragma unroll
    for (int pass = 0; pass < 8; ++pass) {
        int f = t + pass * 256;
        int plane = f >> 10;
        int rem = f & 1023;
        int bi = rem >> 3;
        int y4 = rem & 7;
        float4 v = *reinterpret_cast<const float4*>(
            &Z[(size_t)(plane * 64 + j) * 32768 + (size_t)(p * 128 + bi) * 32 + y4 * 4]);
        *reinterpret_cast<float4*>(&Zs[plane][bi >> 5][bi & 31][y4 * 4]) = v;
    }
    __syncthreads();

    const int o_l = t >> 7;
    const int bb  = (t >> 5) & 3;
    const int y   = t & 31;

    for (int o0 = 0; o0 < 32; o0 += 2) {
#pragma unroll
        for (int pass = 0; pass < 4; ++pass) {
            int f = t + pass * 256;
            int ol = f >> 9;
            int plane = (f >> 8) & 1;
            int i = (f >> 3) & 31;
            int y4 = f & 7;
            const float* wp = plane ? wim : wre;
            float4 v = *reinterpret_cast<const float4*>(
                &wp[((((size_t)(i * 32 + o0 + ol)) * 8 + p) * 32 + x) * 32 + y4 * 4]);
            *reinterpret_cast<float4*>(&Ws[ol][plane][i][y4 * 4]) = v;
        }
        __syncthreads();
        float accre = 0.f, accim = 0.f;
#pragma unroll
        for (int i = 0; i < 32; ++i) {
            float zre = Zs[0][bb][i][y], zim = Zs[1][bb][i][y];
            float wr  = Ws[o_l][0][i][y], wi = Ws[o_l][1][i][y];
            accre += zre * wr - zim * wi;
            accim += zre * wi + zim * wr;
        }
        int o = o0 + o_l;
        size_t col = (size_t)(p * 128 + bb * 32 + o) * 32 + y;
        Z3[(size_t)j * 32768 + col]        = accre;
        Z3[(size_t)(64 + j) * 32768 + col] = accim;
        __syncthreads();
    }
}

// ================= launch =================
extern "C" void kernel_launch(void* const* d_in, const int* in_sizes, int n_in,
                              void* d_out, int out_size) {
    const float* x    = (const float*)d_in[0];
    const float* w1re = (const float*)d_in[1];
    const float* w1im = (const float*)d_in[2];
    const float* w4re = (const float*)d_in[3];
    const float* w4im = (const float*)d_in[4];
    float* out = (float*)d_out;

    void *pY, *pZ, *pZ3, *pVh, *pVl, *pT1, *pA2, *pA4, *pT5;
    cudaGetSymbolAddress(&pY,  g_Y);
    cudaGetSymbolAddress(&pZ,  g_Z);
    cudaGetSymbolAddress(&pZ3, g_Z3);
    cudaGetSymbolAddress(&pVh, g_Vh);
    cudaGetSymbolAddress(&pVl, g_Vl);
    cudaGetSymbolAddress(&pT1, g_T1);
    cudaGetSymbolAddress(&pA2, g_A2);
    cudaGetSymbolAddress(&pA4, g_A4);
    cudaGetSymbolAddress(&pT5, g_T5);

    auto s1k = mgemm<128, 64, 64, 4, 2, 256L, 64L, 0, 1>;
    auto s2k = mgemm<128, 64, 64, 4, 2, 512L, 32768L, 0, 0>;
    auto s4k = mgemm<128, 64, 64, 4, 2, 128L, 32768L, 0, 2>;
    auto s5k = mgemm<64, 128, 64, 2, 4, 64L, 256L, 1, 3>;
    cudaFuncSetAttribute(s1k, cudaFuncAttributeMaxDynamicSharedMemorySize, 55296);
    cudaFuncSetAttribute(s2k, cudaFuncAttributeMaxDynamicSharedMemorySize, 55296);
    cudaFuncSetAttribute(s4k, cudaFuncAttributeMaxDynamicSharedMemorySize, 55296);
    cudaFuncSetAttribute(s5k, cudaFuncAttributeMaxDynamicSharedMemorySize, 53248);

    init_tables<<<256, 256>>>();

    // S1: Y(262144x64) = x(262144x256) * T1(256x64)  -> plane scatter
    s1k<<<dim3(2048, 1), 256, 55296>>>(x, nullptr, nullptr, (const float*)pT1, (float*)pY);

    // S2: Z(128x32768) = A2(128x512) * Y(512x32768)
    s2k<<<dim3(1, 512), 256, 55296>>>((const float*)pA2, nullptr, nullptr,
                                      (const float*)pY, (float*)pZ);

    // S3: channel mixing
    chanmix<<<512, 256>>>((const float*)pZ, w1re, w1im, w4re, w4im, (float*)pZ3);

    // S4: V(512x32768) = A4(512x128) * Z3(128x32768) -> bf16 hi/lo emit
    //     grid.y MUST be NTOT/BN = 32768/64 = 512  (round-6 bug: was 128)
    s4k<<<dim3(4, 512), 256, 55296>>>((const float*)pA4, nullptr, nullptr,
                                      (const float*)pZ3, nullptr);

    // S5: out(262144x256) = V(262144x64) * T5(64x256)
    s5k<<<dim3(4096, 2), 256, 53248>>>(nullptr, (const ushort_t*)pVh, (const ushort_t*)pVl,
                                       (const float*)pT5, out);
}

// round 8
// speedup vs baseline: 1.7552x; 1.0367x over previous
#include <cuda_runtime.h>
#include <cuda_bf16.h>
#include <cstdint>

// P=8, B=4, C=32, H=256, W=256, M1=M2=32
// rows R = P*B*C*H = 262144 ; pbc = P*B*C = 1024 ; cols (pbc,y) = 32768

typedef unsigned short ushort_t;

// ================= helpers =================
__device__ __forceinline__ uint32_t smem_u32(const void* p) {
    uint32_t a;
    asm("{ .reg .u64 t; cvta.to.shared.u64 t, %1; cvt.u32.u64 %0, t; }" : "=r"(a) : "l"(p));
    return a;
}
__device__ __forceinline__ void ldm4(uint32_t* r, uint32_t a) {
    asm volatile("ldmatrix.sync.aligned.m8n8.x4.shared.b16 {%0,%1,%2,%3}, [%4];"
                 : "=r"(r[0]), "=r"(r[1]), "=r"(r[2]), "=r"(r[3]) : "r"(a));
}
__device__ __forceinline__ void ldm4t(uint32_t* r, uint32_t a) {
    asm volatile("ldmatrix.sync.aligned.m8n8.x4.trans.shared.b16 {%0,%1,%2,%3}, [%4];"
                 : "=r"(r[0]), "=r"(r[1]), "=r"(r[2]), "=r"(r[3]) : "r"(a));
}
__device__ __forceinline__ void mma16816(float* c, const uint32_t* a, const uint32_t* b) {
    asm volatile("mma.sync.aligned.m16n8k16.row.col.f32.bf16.bf16.f32 "
                 "{%0,%1,%2,%3}, {%4,%5,%6,%7}, {%8,%9}, {%0,%1,%2,%3};"
                 : "+f"(c[0]), "+f"(c[1]), "+f"(c[2]), "+f"(c[3])
                 : "r"(a[0]), "r"(a[1]), "r"(a[2]), "r"(a[3]), "r"(b[0]), "r"(b[1]));
}
__device__ __forceinline__ void bsplit(float v, ushort_t& h, ushort_t& l) {
    __nv_bfloat16 bh = __float2bfloat16(v);
    __nv_bfloat16 bl = __float2bfloat16(v - __bfloat162float(bh));
    h = __bfloat16_as_ushort(bh);
    l = __bfloat16_as_ushort(bl);
}

// ================= scratch =================
__device__ __align__(16) ushort_t g_Yh[512u * 32768];       // [plane*256+h][pbc*32+y]
__device__ __align__(16) ushort_t g_Yl[512u * 32768];
__device__ __align__(16) float    g_Z [128u * 32768];       // [plane*64+j][col] fp32
__device__ __align__(16) ushort_t g_Z3h[128u * 32768];      // hi/lo
__device__ __align__(16) ushort_t g_Z3l[128u * 32768];
__device__ __align__(16) ushort_t g_Vh[262144u * 64];       // [row][64]
__device__ __align__(16) ushort_t g_Vl[262144u * 64];
__device__ __align__(16) ushort_t g_T1h[256 * 64], g_T1l[256 * 64];    // [k=w][n]
__device__ __align__(16) ushort_t g_A2h[128 * 512], g_A2l[128 * 512];  // [row][k]
__device__ __align__(16) ushort_t g_A4h[512 * 128], g_A4l[512 * 128];  // [row][k]
__device__ __align__(16) ushort_t g_T5h[64 * 256], g_T5l[64 * 256];    // [k][n=w]

// ================= table init (pre-split to bf16 hi/lo) =================
__global__ void init_tables() {
    int t = blockIdx.x * 256 + threadIdx.x;   // 0..65535
    ushort_t h, l;
    if (t < 256 * 64) {     // T1 [w][c]: c<32 cos, c>=32 -sin
        int w = t >> 6, c = t & 63, y = c & 31;
        int m = (w * y) & 255;
        double s, ct; sincospi(2.0 * m / 256.0, &s, &ct);
        bsplit((c < 32) ? (float)ct : (float)(-s), h, l);
        g_T1h[t] = h; g_T1l[t] = l;
    }
    {                       // A2 128x512
        int r = t >> 9, k = t & 511;
        int pk = k >> 8, hh = k & 255;
        int j = r & 63;
        int xr = (j < 32) ? j : (192 + j);
        int m = (xr * hh) & 255;
        double s, ct; sincospi(2.0 * m / 256.0, &s, &ct);
        float v;
        if (r < 64) v = (pk == 0) ? (float)ct : (float)s;
        else        v = (pk == 0) ? (float)(-s) : (float)ct;
        bsplit(v, h, l);
        g_A2h[t] = h; g_A2l[t] = l;
    }
    {                       // A4 512x128
        int r = t >> 7, c = t & 127;
        int pr = r >> 8, hh = r & 255;
        int pc = c >> 6, j = c & 63;
        int xr = (j < 32) ? j : (192 + j);
        int m = (xr * hh) & 255;
        double s, ct; sincospi(2.0 * m / 256.0, &s, &ct);
        float v;
        if (pr == 0) v = (pc == 0) ? (float)ct : (float)(-s);
        else         v = (pc == 0) ? (float)s  : (float)ct;
        bsplit(v, h, l);
        g_A4h[t] = h; g_A4l[t] = l;
    }
    if (t < 64 * 256) {     // T5 [k|32+k][w]
        int r = t >> 8, w = t & 255, k = r & 31;
        int m = (k * w) & 255;
        double s, ct; sincospi(2.0 * m / 256.0, &s, &ct);
        double coef = ((k == 0) ? 1.0 : 2.0) / 65536.0;
        bsplit((r < 32) ? (float)(coef * ct) : (float)(-coef * s), h, l);
        g_T5h[t] = h; g_T5l[t] = l;
    }
}

// ================= unified pipelined warp-MMA GEMM =================
// C(M x NTOT) = A(M x KDIM) * B(KDIM x NTOT), bf16 hi/lo 3-pass.
// AMODE 0: A fp32 (convert+split in kernel).  AMODE 1: A pre-split (Ahg/Alg, stride KDIM).
// BMODE 0: B fp32.                            BMODE 1: B pre-split (Bhg/Blg, stride NTOT).
// CMODE 0: row-major f32 C.
// CMODE 1: S1 plane scatter -> g_Yh/g_Yl [plane*256+h][pbc*32+y] (staged).
// CMODE 2: S4 emit -> g_Vh/g_Vl [(pbc*256+h)][plane*32+y].
// CMODE 3: row-major f32 C via coalescing stage.
template<int BM, int BN, int BK, int WM, int WN, long KDIM, long NTOT,
         int AMODE, int BMODE, int CMODE>
__global__ void __launch_bounds__(256, 2) mgemm(
    const float* __restrict__ Af, const ushort_t* __restrict__ Ahg,
    const ushort_t* __restrict__ Alg, const float* __restrict__ Bf,
    const ushort_t* __restrict__ Bhg, const ushort_t* __restrict__ Blg,
    float* __restrict__ Cf)
{
    constexpr int TWM = BM / WM, TWN = BN / WN, MT = TWM / 16, NT = TWN / 8;
    constexpr int BKP = BK + 8, BNP = BN + 8;
    constexpr int PA = BM * BKP * 2;            // bytes per A plane
    constexpr int PB = BK * BNP * 2;            // bytes per B plane
    constexpr int OAH = 0, OAL = PA, OBH = 2 * PA, OBL = 2 * PA + PB;
    constexpr int AF4 = BM * BK / 1024, BF4 = BK * BN / 1024;
    constexpr long KT = KDIM / BK;
    static_assert(WM * WN == 8 && (NT % 2) == 0, "cfg");

    extern __shared__ char smem[];
    const uint32_t sb = smem_u32(smem);
    const int t = threadIdx.x, wid = t >> 5, lane = t & 31;
    const int wm = wid / WN, wn = wid % WN;
    const long rowBase = (long)blockIdx.x * BM;
    const long colBase = (long)blockIdx.y * BN;

    float4 aReg[AMODE == 0 ? AF4 : 1];
    uint2  ahReg[AMODE == 1 ? AF4 : 1], alReg[AMODE == 1 ? AF4 : 1];
    float4 bReg[BMODE == 0 ? BF4 : 1];
    uint2  bhReg[BMODE == 1 ? BF4 : 1], blReg[BMODE == 1 ? BF4 : 1];
    float  acc[MT][NT][4];
#pragma unroll
    for (int i = 0; i < MT; ++i)
#pragma unroll
        for (int j = 0; j < NT; ++j)
#pragma unroll
            for (int q = 0; q < 4; ++q) acc[i][j][q] = 0.f;

    auto loadG = [&](long k0) {
#pragma unroll
        for (int f4 = 0; f4 < AF4; ++f4) {
            int f = t + f4 * 256;
            int ar = f / (BK / 4), ac = f % (BK / 4);
            if constexpr (AMODE == 0) {
                aReg[f4] = *reinterpret_cast<const float4*>(
                    &Af[(rowBase + ar) * KDIM + k0 + ac * 4]);
            } else {
                ahReg[f4] = *reinterpret_cast<const uint2*>(
                    &Ahg[(rowBase + ar) * KDIM + k0 + ac * 4]);
                alReg[f4] = *reinterpret_cast<const uint2*>(
                    &Alg[(rowBase + ar) * KDIM + k0 + ac * 4]);
            }
        }
#pragma unroll
        for (int f4 = 0; f4 < BF4; ++f4) {
            int f = t + f4 * 256;
            int br = f / (BN / 4), bc = f % (BN / 4);
            if constexpr (BMODE == 0) {
                bReg[f4] = *reinterpret_cast<const float4*>(
                    &Bf[(k0 + br) * NTOT + colBase + bc * 4]);
            } else {
                bhReg[f4] = *reinterpret_cast<const uint2*>(
                    &Bhg[(k0 + br) * NTOT + colBase + bc * 4]);
                blReg[f4] = *reinterpret_cast<const uint2*>(
                    &Blg[(k0 + br) * NTOT + colBase + bc * 4]);
            }
        }
    };
    auto storeS = [&]() {
#pragma unroll
        for (int f4 = 0; f4 < AF4; ++f4) {
            int f = t + f4 * 256;
            int ar = f / (BK / 4), ac = f % (BK / 4);
            uint32_t off = (uint32_t)(ar * BKP + ac * 4) * 2;
            if constexpr (AMODE == 0) {
                float fv[4] = {aReg[f4].x, aReg[f4].y, aReg[f4].z, aReg[f4].w};
                ushort_t hs[4], ls[4];
#pragma unroll
                for (int q = 0; q < 4; ++q) bsplit(fv[q], hs[q], ls[q]);
                *reinterpret_cast<uint2*>(smem + OAH + off) =
                    make_uint2(hs[0] | ((uint32_t)hs[1] << 16), hs[2] | ((uint32_t)hs[3] << 16));
                *reinterpret_cast<uint2*>(smem + OAL + off) =
                    make_uint2(ls[0] | ((uint32_t)ls[1] << 16), ls[2] | ((uint32_t)ls[3] << 16));
            } else {
                *reinterpret_cast<uint2*>(smem + OAH + off) = ahReg[f4];
                *reinterpret_cast<uint2*>(smem + OAL + off) = alReg[f4];
            }
        }
#pragma unroll
        for (int f4 = 0; f4 < BF4; ++f4) {
            int f = t + f4 * 256;
            int br = f / (BN / 4), bc = f % (BN / 4);
            uint32_t off = (uint32_t)(br * BNP + bc * 4) * 2;
            if constexpr (BMODE == 0) {
                float fv[4] = {bReg[f4].x, bReg[f4].y, bReg[f4].z, bReg[f4].w};
                ushort_t hs[4], ls[4];
#pragma unroll
                for (int q = 0; q < 4; ++q) bsplit(fv[q], hs[q], ls[q]);
                *reinterpret_cast<uint2*>(smem + OBH + off) =
                    make_uint2(hs[0] | ((uint32_t)hs[1] << 16), hs[2] | ((uint32_t)hs[3] << 16));
                *reinterpret_cast<uint2*>(smem + OBL + off) =
                    make_uint2(ls[0] | ((uint32_t)ls[1] << 16), ls[2] | ((uint32_t)ls[3] << 16));
            } else {
                *reinterpret_cast<uint2*>(smem + OBH + off) = bhReg[f4];
                *reinterpret_cast<uint2*>(smem + OBL + off) = blReg[f4];
            }
        }
    };
    auto compute = [&]() {
#pragma unroll
        for (int ks = 0; ks < BK / 16; ++ks) {
            const int k0 = ks * 16;
            uint32_t ah[MT][4], al[MT][4];
#pragma unroll
            for (int i = 0; i < MT; ++i) {
                int row = wm * TWM + i * 16 + (lane & 15);
                int col = k0 + ((lane >> 4) << 3);
                uint32_t off = (uint32_t)(row * BKP + col) * 2;
                ldm4(ah[i], sb + OAH + off);
                ldm4(al[i], sb + OAL + off);
            }
#pragma unroll
            for (int pr = 0; pr < NT / 2; ++pr) {
                uint32_t bh[4], bl[4];
                int krow = k0 + ((lane >> 3) & 1) * 8 + (lane & 7);
                int coln = wn * TWN + (pr * 2 + (lane >> 4)) * 8;
                uint32_t boff = (uint32_t)(krow * BNP + coln) * 2;
                ldm4t(bh, sb + OBH + boff);
                ldm4t(bl, sb + OBL + boff);
#pragma unroll
                for (int i = 0; i < MT; ++i)
#pragma unroll
                    for (int nn = 0; nn < 2; ++nn) {
                        float* c = acc[i][pr * 2 + nn];
                        mma16816(c, ah[i], bh + nn * 2);
                        mma16816(c, al[i], bh + nn * 2);
                        mma16816(c, ah[i], bl + nn * 2);
                    }
            }
        }
    };

    loadG(0);
    storeS();
    __syncthreads();
#pragma unroll 1
    for (long kt = 1; kt < KT; ++kt) {
        loadG(kt * BK);
        compute();
        __syncthreads();
        storeS();
        __syncthreads();
    }
    compute();

    const int g = lane >> 2, tq = lane & 3;
    if constexpr (CMODE == 0) {
#pragma unroll
        for (int i = 0; i < MT; ++i)
#pragma unroll
            for (int j = 0; j < NT; ++j) {
                const float* c = acc[i][j];
                long r0 = rowBase + wm * TWM + i * 16 + g;
                long c0 = colBase + wn * TWN + j * 8 + tq * 2;
                *reinterpret_cast<float2*>(&Cf[r0 * NTOT + c0])       = make_float2(c[0], c[1]);
                *reinterpret_cast<float2*>(&Cf[(r0 + 8) * NTOT + c0]) = make_float2(c[2], c[3]);
            }
    } else if constexpr (CMODE == 2) {
#pragma unroll
        for (int i = 0; i < MT; ++i)
#pragma unroll
            for (int j = 0; j < NT; ++j) {
                const float* c = acc[i][j];
                long r0 = rowBase + wm * TWM + i * 16 + g;
                long c0 = colBase + wn * TWN + j * 8 + tq * 2;
                long pbc = c0 >> 5, y = c0 & 31;
#pragma unroll
                for (int rr = 0; rr < 2; ++rr) {
                    long r = r0 + rr * 8;
                    long plane = r >> 8, h = r & 255;
                    long addr = (pbc * 256 + h) * 64 + plane * 32 + y;
                    ushort_t h0, l0, h1, l1;
                    bsplit(c[rr * 2], h0, l0);
                    bsplit(c[rr * 2 + 1], h1, l1);
                    *reinterpret_cast<uint32_t*>(&g_Vh[addr]) = h0 | ((uint32_t)h1 << 16);
                    *reinterpret_cast<uint32_t*>(&g_Vl[addr]) = l0 | ((uint32_t)l1 << 16);
                }
            }
    } else {
        // staged: CMODE 1 (Y hi/lo plane scatter) / CMODE 3 (row-major f32)
        constexpr int STOFF = (CMODE == 3) ? OBH : 0;
        float* stage = reinterpret_cast<float*>(smem + STOFF);
        __syncthreads();
#pragma unroll
        for (int i = 0; i < MT; ++i)
#pragma unroll
            for (int j = 0; j < NT; ++j) {
                const float* c = acc[i][j];
                int row = wm * TWM + i * 16 + g;
                int col = wn * TWN + j * 8 + tq * 2;
                *reinterpret_cast<float2*>(&stage[row * (BN + 4) + col])       = make_float2(c[0], c[1]);
                *reinterpret_cast<float2*>(&stage[(row + 8) * (BN + 4) + col]) = make_float2(c[2], c[3]);
            }
        __syncthreads();
        if constexpr (CMODE == 1) {
            const long pbc = rowBase >> 8;
            const int hb = (int)(rowBase & 255);
#pragma unroll
            for (int it = 0; it < BM * BN / 1024; ++it) {
                int idx = t + it * 256;
                int r = idx / (BN / 4), c4 = idx % (BN / 4);
                float4 v = *reinterpret_cast<float4*>(&stage[r * (BN + 4) + c4 * 4]);
                int c = c4 * 4, plane = c >> 5, y = c & 31;
                float fv[4] = {v.x, v.y, v.z, v.w};
                ushort_t hs[4], ls[4];
#pragma unroll
                for (int q = 0; q < 4; ++q) bsplit(fv[q], hs[q], ls[q]);
                long addr = (long)(plane * 256 + hb + r) * 32768L + pbc * 32 + y;
                *reinterpret_cast<uint2*>(&g_Yh[addr]) =
                    make_uint2(hs[0] | ((uint32_t)hs[1] << 16), hs[2] | ((uint32_t)hs[3] << 16));
                *reinterpret_cast<uint2*>(&g_Yl[addr]) =
                    make_uint2(ls[0] | ((uint32_t)ls[1] << 16), ls[2] | ((uint32_t)ls[3] << 16));
            }
        } else {
#pragma unroll
            for (int it = 0; it < BM * BN / 1024; ++it) {
                int idx = t + it * 256;
                int r = idx / (BN / 4), c4 = idx % (BN / 4);
                float4 v = *reinterpret_cast<float4*>(&stage[r * (BN + 4) + c4 * 4]);
                *reinterpret_cast<float4*>(&Cf[(rowBase + r) * NTOT + colBase + c4 * 4]) = v;
            }
        }
    }
}

// ================= channel mix (512 threads, emits Z3 hi/lo) =================
__global__ void __launch_bounds__(512) chanmix(const float* __restrict__ Z,
                                               const float* __restrict__ w1re,
                                               const float* __restrict__ w1im,
                                               const float* __restrict__ w4re,
                                               const float* __restrict__ w4im) {
    __shared__ float Zs[2][4][32][32];   // plane, b, i, y   (32KB)
    __shared__ float Ws[4][2][32][32];   // o_l, plane, i, y (16KB)
    const int t = threadIdx.x;
    const int p = blockIdx.x >> 6;
    const int j = blockIdx.x & 63;
    const int x = j & 31;
    const float* wre = (j < 32) ? w1re : w4re;
    const float* wim = (j < 32) ? w1im : w4im;

#pragma unroll
    for (int pass = 0; pass < 4; ++pass) {
        int f = t + pass * 512;
        int plane = f >> 10;
        int rem = f & 1023;
        int bi = rem >> 3;
        int y4 = rem & 7;
        float4 v = *reinterpret_cast<const float4*>(
            &Z[(size_t)(plane * 64 + j) * 32768 + (size_t)(p * 128 + bi) * 32 + y4 * 4]);
        *reinterpret_cast<float4*>(&Zs[plane][bi >> 5][bi & 31][y4 * 4]) = v;
    }
    __syncthreads();

    const int o_l = t >> 7;
    const int bb  = (t >> 5) & 3;
    const int y   = t & 31;

    for (int o0 = 0; o0 < 32; o0 += 4) {
#pragma unroll
        for (int pass = 0; pass < 4; ++pass) {
            int f = t + pass * 512;
            int ol = f >> 9;
            int plane = (f >> 8) & 1;
            int i = (f >> 3) & 31;
            int y4 = f & 7;
            const float* wp = plane ? wim : wre;
            float4 v = *reinterpret_cast<const float4*>(
                &wp[((((size_t)(i * 32 + o0 + ol)) * 8 + p) * 32 + x) * 32 + y4 * 4]);
            *reinterpret_cast<float4*>(&Ws[ol][plane][i][y4 * 4]) = v;
        }
        __syncthreads();
        float accre = 0.f, accim = 0.f;
#pragma unroll
        for (int i = 0; i < 32; ++i) {
            float zre = Zs[0][bb][i][y], zim = Zs[1][bb][i][y];
            float wr  = Ws[o_l][0][i][y], wi = Ws[o_l][1][i][y];
            accre += zre * wr - zim * wi;
            accim += zre * wi + zim * wr;
        }
        int o = o0 + o_l;
        size_t col = (size_t)(p * 128 + bb * 32 + o) * 32 + y;
        ushort_t hr, lr, hi, li;
        bsplit(accre, hr, lr);
        bsplit(accim, hi, li);
        g_Z3h[(size_t)j * 32768 + col]        = hr;
        g_Z3l[(size_t)j * 32768 + col]        = lr;
        g_Z3h[(size_t)(64 + j) * 32768 + col] = hi;
        g_Z3l[(size_t)(64 + j) * 32768 + col] = li;
        __syncthreads();
    }
}

// ================= launch =================
extern "C" void kernel_launch(void* const* d_in, const int* in_sizes, int n_in,
                              void* d_out, int out_size) {
    const float* x    = (const float*)d_in[0];
    const float* w1re = (const float*)d_in[1];
    const float* w1im = (const float*)d_in[2];
    const float* w4re = (const float*)d_in[3];
    const float* w4im = (const float*)d_in[4];
    float* out = (float*)d_out;

    void *pYh, *pYl, *pZ, *pZ3h, *pZ3l, *pVh, *pVl;
    void *pT1h, *pT1l, *pA2h, *pA2l, *pA4h, *pA4l, *pT5h, *pT5l;
    cudaGetSymbolAddress(&pYh,  g_Yh);
    cudaGetSymbolAddress(&pYl,  g_Yl);
    cudaGetSymbolAddress(&pZ,   g_Z);
    cudaGetSymbolAddress(&pZ3h, g_Z3h);
    cudaGetSymbolAddress(&pZ3l, g_Z3l);
    cudaGetSymbolAddress(&pVh,  g_Vh);
    cudaGetSymbolAddress(&pVl,  g_Vl);
    cudaGetSymbolAddress(&pT1h, g_T1h);
    cudaGetSymbolAddress(&pT1l, g_T1l);
    cudaGetSymbolAddress(&pA2h, g_A2h);
    cudaGetSymbolAddress(&pA2l, g_A2l);
    cudaGetSymbolAddress(&pA4h, g_A4h);
    cudaGetSymbolAddress(&pA4l, g_A4l);
    cudaGetSymbolAddress(&pT5h, g_T5h);
    cudaGetSymbolAddress(&pT5l, g_T5l);

    // S1: A=x fp32, B=T1 presplit, C -> Y hi/lo plane scatter
    auto s1k = mgemm<128, 64, 64, 4, 2, 256L, 64L, 0, 1, 1>;
    // S2: A=A2 presplit, B=Y presplit, C -> Z fp32 row-major
    auto s2k = mgemm<128, 64, 64, 4, 2, 512L, 32768L, 1, 1, 0>;
    // S4: A=A4 presplit, B=Z3 presplit, C -> V hi/lo emit
    auto s4k = mgemm<128, 64, 64, 4, 2, 128L, 32768L, 1, 1, 2>;
    // S5: A=V presplit, B=T5 presplit, C -> out f32 staged
    auto s5k = mgemm<64, 128, 64, 2, 4, 64L, 256L, 1, 1, 3>;
    cudaFuncSetAttribute(s1k, cudaFuncAttributeMaxDynamicSharedMemorySize, 55296);
    cudaFuncSetAttribute(s2k, cudaFuncAttributeMaxDynamicSharedMemorySize, 55296);
    cudaFuncSetAttribute(s4k, cudaFuncAttributeMaxDynamicSharedMemorySize, 55296);
    cudaFuncSetAttribute(s5k, cudaFuncAttributeMaxDynamicSharedMemorySize, 53248);

    init_tables<<<256, 256>>>();

    // S1: Y(262144x64) = x(262144x256) * T1(256x64)
    s1k<<<dim3(2048, 1), 256, 55296>>>(x, nullptr, nullptr, nullptr,
                                       (const ushort_t*)pT1h, (const ushort_t*)pT1l, nullptr);

    // S2: Z(128x32768) = A2(128x512) * Y(512x32768)
    s2k<<<dim3(1, 512), 256, 55296>>>(nullptr, (const ushort_t*)pA2h, (const ushort_t*)pA2l,
                                      nullptr, (const ushort_t*)pYh, (const ushort_t*)pYl,
                                      (float*)pZ);

    // S3: channel mixing (emits Z3 hi/lo)
    chanmix<<<512, 512>>>((const float*)pZ, w1re, w1im, w4re, w4im);

    // S4: V(512x32768) = A4(512x128) * Z3(128x32768)  [grid.y = 32768/64 = 512]
    s4k<<<dim3(4, 512), 256, 55296>>>(nullptr, (const ushort_t*)pA4h, (const ushort_t*)pA4l,
                                      nullptr, (const ushort_t*)pZ3h, (const ushort_t*)pZ3l,
                                      nullptr);

    // S5: out(262144x256) = V(262144x64) * T5(64x256)
    s5k<<<dim3(4096, 2), 256, 53248>>>(nullptr, (const ushort_t*)pVh, (const ushort_t*)pVl,
                                       nullptr, (const ushort_t*)pT5h, (const ushort_t*)pT5l,
                                       out);
}

// round 9
// speedup vs baseline: 1.8765x; 1.0691x over previous
#include <cuda_runtime.h>
#include <cuda_bf16.h>
#include <cstdint>

// P=8, B=4, C=32, H=256, W=256, M1=M2=32
// rows R = P*B*C*H = 262144 ; pbc = P*B*C = 1024 ; cols (pbc,y) = 32768

typedef unsigned short ushort_t;

// ================= helpers =================
__device__ __forceinline__ uint32_t smem_u32(const void* p) {
    uint32_t a;
    asm("{ .reg .u64 t; cvta.to.shared.u64 t, %1; cvt.u32.u64 %0, t; }" : "=r"(a) : "l"(p));
    return a;
}
__device__ __forceinline__ void ldm4(uint32_t* r, uint32_t a) {
    asm volatile("ldmatrix.sync.aligned.m8n8.x4.shared.b16 {%0,%1,%2,%3}, [%4];"
                 : "=r"(r[0]), "=r"(r[1]), "=r"(r[2]), "=r"(r[3]) : "r"(a));
}
__device__ __forceinline__ void ldm4t(uint32_t* r, uint32_t a) {
    asm volatile("ldmatrix.sync.aligned.m8n8.x4.trans.shared.b16 {%0,%1,%2,%3}, [%4];"
                 : "=r"(r[0]), "=r"(r[1]), "=r"(r[2]), "=r"(r[3]) : "r"(a));
}
__device__ __forceinline__ void mma16816(float* c, const uint32_t* a, const uint32_t* b) {
    asm volatile("mma.sync.aligned.m16n8k16.row.col.f32.bf16.bf16.f32 "
                 "{%0,%1,%2,%3}, {%4,%5,%6,%7}, {%8,%9}, {%0,%1,%2,%3};"
                 : "+f"(c[0]), "+f"(c[1]), "+f"(c[2]), "+f"(c[3])
                 : "r"(a[0]), "r"(a[1]), "r"(a[2]), "r"(a[3]), "r"(b[0]), "r"(b[1]));
}
__device__ __forceinline__ void bsplit(float v, ushort_t& h, ushort_t& l) {
    __nv_bfloat16 bh = __float2bfloat16(v);
    __nv_bfloat16 bl = __float2bfloat16(v - __bfloat162float(bh));
    h = __bfloat16_as_ushort(bh);
    l = __bfloat16_as_ushort(bl);
}
__device__ __forceinline__ void cpa16(uint32_t saddr, const void* g) {
    asm volatile("cp.async.cg.shared.global [%0], [%1], 16;" :: "r"(saddr), "l"(g));
}
#define CPA_COMMIT() asm volatile("cp.async.commit_group;" ::: "memory")
#define CPA_WAIT0()  asm volatile("cp.async.wait_group 0;" ::: "memory")

// ================= scratch =================
__device__ __align__(16) ushort_t g_Yh[512u * 32768];       // [plane*256+h][pbc*32+y]
__device__ __align__(16) ushort_t g_Yl[512u * 32768];
__device__ __align__(16) float    g_Z [128u * 32768];       // [plane*64+j][col] fp32
__device__ __align__(16) ushort_t g_Z3h[128u * 32768];
__device__ __align__(16) ushort_t g_Z3l[128u * 32768];
__device__ __align__(16) ushort_t g_Vh[262144u * 64];       // [row][64]
__device__ __align__(16) ushort_t g_Vl[262144u * 64];
__device__ __align__(16) ushort_t g_T1h[256 * 64], g_T1l[256 * 64];    // [k=w][n]
__device__ __align__(16) ushort_t g_A2h[128 * 512], g_A2l[128 * 512];  // [row][k]
__device__ __align__(16) ushort_t g_A4h[512 * 128], g_A4l[512 * 128];  // [row][k]
__device__ __align__(16) ushort_t g_T5h[64 * 256], g_T5l[64 * 256];    // [k][n=w]

// ================= table init (pre-split to bf16 hi/lo) =================
__global__ void init_tables() {
    int t = blockIdx.x * 256 + threadIdx.x;   // 0..65535
    ushort_t h, l;
    if (t < 256 * 64) {     // T1 [w][c]
        int w = t >> 6, c = t & 63, y = c & 31;
        int m = (w * y) & 255;
        double s, ct; sincospi(2.0 * m / 256.0, &s, &ct);
        bsplit((c < 32) ? (float)ct : (float)(-s), h, l);
        g_T1h[t] = h; g_T1l[t] = l;
    }
    {                       // A2 128x512
        int r = t >> 9, k = t & 511;
        int pk = k >> 8, hh = k & 255;
        int j = r & 63;
        int xr = (j < 32) ? j : (192 + j);
        int m = (xr * hh) & 255;
        double s, ct; sincospi(2.0 * m / 256.0, &s, &ct);
        float v;
        if (r < 64) v = (pk == 0) ? (float)ct : (float)s;
        else        v = (pk == 0) ? (float)(-s) : (float)ct;
        bsplit(v, h, l);
        g_A2h[t] = h; g_A2l[t] = l;
    }
    {                       // A4 512x128
        int r = t >> 7, c = t & 127;
        int pr = r >> 8, hh = r & 255;
        int pc = c >> 6, j = c & 63;
        int xr = (j < 32) ? j : (192 + j);
        int m = (xr * hh) & 255;
        double s, ct; sincospi(2.0 * m / 256.0, &s, &ct);
        float v;
        if (pr == 0) v = (pc == 0) ? (float)ct : (float)(-s);
        else         v = (pc == 0) ? (float)s  : (float)ct;
        bsplit(v, h, l);
        g_A4h[t] = h; g_A4l[t] = l;
    }
    if (t < 64 * 256) {     // T5 [k|32+k][w]
        int r = t >> 8, w = t & 255, k = r & 31;
        int m = (k * w) & 255;
        double s, ct; sincospi(2.0 * m / 256.0, &s, &ct);
        double coef = ((k == 0) ? 1.0 : 2.0) / 65536.0;
        bsplit((r < 32) ? (float)(coef * ct) : (float)(-coef * s), h, l);
        g_T5h[t] = h; g_T5l[t] = l;
    }
}

// ================= double-buffered cp.async warp-MMA GEMM =================
// C(M x NTOT) = A(M x KDIM) * B(KDIM x NTOT), bf16 hi/lo 3-pass.
// AMODE 0: A fp32 (register convert+split).  AMODE 1: A pre-split via cp.async.
// B always pre-split via cp.async.
// CMODE 0: row-major f32.  CMODE 1: -> g_Yh/g_Yl plane scatter (staged).
// CMODE 2: -> g_Vh/g_Vl emit.  CMODE 3: row-major f32 via coalescing stage.
template<int BM, int BN, int BK, int WM, int WN, long KDIM, long NTOT,
         int AMODE, int CMODE>
__global__ void __launch_bounds__(256, 2) mgemm(
    const float* __restrict__ Af, const ushort_t* __restrict__ Ahg,
    const ushort_t* __restrict__ Alg,
    const ushort_t* __restrict__ Bhg, const ushort_t* __restrict__ Blg,
    float* __restrict__ Cf)
{
    constexpr int TWM = BM / WM, TWN = BN / WN, MT = TWM / 16, NT = TWN / 8;
    constexpr int BKP = BK + 8, BNP = BN + 8;
    constexpr int PA = BM * BKP * 2;            // bytes per A plane
    constexpr int PB = BK * BNP * 2;            // bytes per B plane
    constexpr int OAH = 0, OAL = PA, OBH = 2 * PA, OBL = 2 * PA + PB;
    constexpr int SBUF = 2 * PA + 2 * PB;
    constexpr long KT = KDIM / BK;
    constexpr int NBUF = (KT > 1) ? 2 : 1;
    constexpr int AF4 = BM * BK / 1024;         // float4 per thread (AMODE 0)
    constexpr int AF8 = BM * BK / 2048;         // 16B cp.async per thread per plane
    constexpr int BF8 = BK * BN / 2048;
    static_assert(WM * WN == 8 && (NT % 2) == 0, "cfg");

    extern __shared__ char smem[];
    const uint32_t sb = smem_u32(smem);
    const int t = threadIdx.x, wid = t >> 5, lane = t & 31;
    const int wm = wid / WN, wn = wid % WN;
    const long rowBase = (long)blockIdx.x * BM;
    const long colBase = (long)blockIdx.y * BN;

    float4 aReg[AMODE == 0 ? AF4 : 1];
    float  acc[MT][NT][4];
#pragma unroll
    for (int i = 0; i < MT; ++i)
#pragma unroll
        for (int j = 0; j < NT; ++j)
#pragma unroll
            for (int q = 0; q < 4; ++q) acc[i][j][q] = 0.f;

    // issue cp.async fetches for chunk k0 into buffer `buf`
    auto fetchAsync = [&](long k0, int buf) {
        const uint32_t bb = sb + buf * SBUF;
        if constexpr (AMODE == 1) {
#pragma unroll
            for (int f8 = 0; f8 < AF8; ++f8) {
                int f = t + f8 * 256;
                int ar = f / (BK / 8), ac8 = f % (BK / 8);
                uint32_t off = (uint32_t)(ar * BKP + ac8 * 8) * 2;
                cpa16(bb + OAH + off, &Ahg[(rowBase + ar) * KDIM + k0 + ac8 * 8]);
                cpa16(bb + OAL + off, &Alg[(rowBase + ar) * KDIM + k0 + ac8 * 8]);
            }
        }
#pragma unroll
        for (int f8 = 0; f8 < BF8; ++f8) {
            int f = t + f8 * 256;
            int br = f / (BN / 8), bc8 = f % (BN / 8);
            uint32_t off = (uint32_t)(br * BNP + bc8 * 8) * 2;
            cpa16(bb + OBH + off, &Bhg[(k0 + br) * NTOT + colBase + bc8 * 8]);
            cpa16(bb + OBL + off, &Blg[(k0 + br) * NTOT + colBase + bc8 * 8]);
        }
    };
    auto loadA = [&](long k0) {   // AMODE 0 only
#pragma unroll
        for (int f4 = 0; f4 < AF4; ++f4) {
            int f = t + f4 * 256;
            int ar = f / (BK / 4), ac = f % (BK / 4);
            aReg[f4] = *reinterpret_cast<const float4*>(
                &Af[(rowBase + ar) * KDIM + k0 + ac * 4]);
        }
    };
    auto storeA = [&](int buf) {  // AMODE 0 only
#pragma unroll
        for (int f4 = 0; f4 < AF4; ++f4) {
            int f = t + f4 * 256;
            int ar = f / (BK / 4), ac = f % (BK / 4);
            float fv[4] = {aReg[f4].x, aReg[f4].y, aReg[f4].z, aReg[f4].w};
            ushort_t hs[4], ls[4];
#pragma unroll
            for (int q = 0; q < 4; ++q) bsplit(fv[q], hs[q], ls[q]);
            uint32_t off = buf * SBUF + (uint32_t)(ar * BKP + ac * 4) * 2;
            *reinterpret_cast<uint2*>(smem + OAH + off) =
                make_uint2(hs[0] | ((uint32_t)hs[1] << 16), hs[2] | ((uint32_t)hs[3] << 16));
            *reinterpret_cast<uint2*>(smem + OAL + off) =
                make_uint2(ls[0] | ((uint32_t)ls[1] << 16), ls[2] | ((uint32_t)ls[3] << 16));
        }
    };
    auto compute = [&](int buf) {
        const uint32_t bb = sb + buf * SBUF;
#pragma unroll
        for (int ks = 0; ks < BK / 16; ++ks) {
            const int k0 = ks * 16;
            uint32_t ah[MT][4], al[MT][4];
#pragma unroll
            for (int i = 0; i < MT; ++i) {
                int row = wm * TWM + i * 16 + (lane & 15);
                int col = k0 + ((lane >> 4) << 3);
                uint32_t off = (uint32_t)(row * BKP + col) * 2;
                ldm4(ah[i], bb + OAH + off);
                ldm4(al[i], bb + OAL + off);
            }
#pragma unroll
            for (int pr = 0; pr < NT / 2; ++pr) {
                uint32_t bh[4], bl[4];
                int krow = k0 + ((lane >> 3) & 1) * 8 + (lane & 7);
                int coln = wn * TWN + (pr * 2 + (lane >> 4)) * 8;
                uint32_t boff = (uint32_t)(krow * BNP + coln) * 2;
                ldm4t(bh, bb + OBH + boff);
                ldm4t(bl, bb + OBL + boff);
#pragma unroll
                for (int i = 0; i < MT; ++i)
#pragma unroll
                    for (int nn = 0; nn < 2; ++nn) {
                        float* c = acc[i][pr * 2 + nn];
                        mma16816(c, ah[i], bh + nn * 2);
                        mma16816(c, al[i], bh + nn * 2);
                        mma16816(c, ah[i], bl + nn * 2);
                    }
            }
        }
    };

    // prologue
    fetchAsync(0, 0);
    CPA_COMMIT();
    if constexpr (AMODE == 0) loadA(0);
    CPA_WAIT0();
    if constexpr (AMODE == 0) storeA(0);
    __syncthreads();

#pragma unroll 1
    for (long kt = 0; kt < KT; ++kt) {
        const int cur = (int)(kt % NBUF);
        const bool more = (kt + 1 < KT);
        if (more) {
            fetchAsync((kt + 1) * BK, cur ^ 1);
            CPA_COMMIT();
            if constexpr (AMODE == 0) loadA((kt + 1) * BK);
        }
        compute(cur);
        if (more) {
            if constexpr (AMODE == 0) storeA(cur ^ 1);
            CPA_WAIT0();
            __syncthreads();
        }
    }

    const int g = lane >> 2, tq = lane & 3;
    if constexpr (CMODE == 0) {
#pragma unroll
        for (int i = 0; i < MT; ++i)
#pragma unroll
            for (int j = 0; j < NT; ++j) {
                const float* c = acc[i][j];
                long r0 = rowBase + wm * TWM + i * 16 + g;
                long c0 = colBase + wn * TWN + j * 8 + tq * 2;
                *reinterpret_cast<float2*>(&Cf[r0 * NTOT + c0])       = make_float2(c[0], c[1]);
                *reinterpret_cast<float2*>(&Cf[(r0 + 8) * NTOT + c0]) = make_float2(c[2], c[3]);
            }
    } else if constexpr (CMODE == 2) {
#pragma unroll
        for (int i = 0; i < MT; ++i)
#pragma unroll
            for (int j = 0; j < NT; ++j) {
                const float* c = acc[i][j];
                long r0 = rowBase + wm * TWM + i * 16 + g;
                long c0 = colBase + wn * TWN + j * 8 + tq * 2;
                long pbc = c0 >> 5, y = c0 & 31;
#pragma unroll
                for (int rr = 0; rr < 2; ++rr) {
                    long r = r0 + rr * 8;
                    long plane = r >> 8, h = r & 255;
                    long addr = (pbc * 256 + h) * 64 + plane * 32 + y;
                    ushort_t h0, l0, h1, l1;
                    bsplit(c[rr * 2], h0, l0);
                    bsplit(c[rr * 2 + 1], h1, l1);
                    *reinterpret_cast<uint32_t*>(&g_Vh[addr]) = h0 | ((uint32_t)h1 << 16);
                    *reinterpret_cast<uint32_t*>(&g_Vl[addr]) = l0 | ((uint32_t)l1 << 16);
                }
            }
    } else {
        // CMODE 1 (Y hi/lo plane scatter, stage at smem+0) / CMODE 3 (f32 staged at OBH)
        constexpr int STOFF = (CMODE == 3) ? OBH : 0;
        float* stage = reinterpret_cast<float*>(smem + STOFF);
        __syncthreads();
#pragma unroll
        for (int i = 0; i < MT; ++i)
#pragma unroll
            for (int j = 0; j < NT; ++j) {
                const float* c = acc[i][j];
                int row = wm * TWM + i * 16 + g;
                int col = wn * TWN + j * 8 + tq * 2;
                *reinterpret_cast<float2*>(&stage[row * (BN + 4) + col])       = make_float2(c[0], c[1]);
                *reinterpret_cast<float2*>(&stage[(row + 8) * (BN + 4) + col]) = make_float2(c[2], c[3]);
            }
        __syncthreads();
        if constexpr (CMODE == 1) {
            const long pbc = rowBase >> 8;
            const int hb = (int)(rowBase & 255);
#pragma unroll
            for (int it = 0; it < BM * BN / 1024; ++it) {
                int idx = t + it * 256;
                int r = idx / (BN / 4), c4 = idx % (BN / 4);
                float4 v = *reinterpret_cast<float4*>(&stage[r * (BN + 4) + c4 * 4]);
                int c = c4 * 4, plane = c >> 5, y = c & 31;
                float fv[4] = {v.x, v.y, v.z, v.w};
                ushort_t hs[4], ls[4];
#pragma unroll
                for (int q = 0; q < 4; ++q) bsplit(fv[q], hs[q], ls[q]);
                long addr = (long)(plane * 256 + hb + r) * 32768L + pbc * 32 + y;
                *reinterpret_cast<uint2*>(&g_Yh[addr]) =
                    make_uint2(hs[0] | ((uint32_t)hs[1] << 16), hs[2] | ((uint32_t)hs[3] << 16));
                *reinterpret_cast<uint2*>(&g_Yl[addr]) =
                    make_uint2(ls[0] | ((uint32_t)ls[1] << 16), ls[2] | ((uint32_t)ls[3] << 16));
            }
        } else {
#pragma unroll
            for (int it = 0; it < BM * BN / 1024; ++it) {
                int idx = t + it * 256;
                int r = idx / (BN / 4), c4 = idx % (BN / 4);
                float4 v = *reinterpret_cast<float4*>(&stage[r * (BN + 4) + c4 * 4]);
                *reinterpret_cast<float4*>(&Cf[(rowBase + r) * NTOT + colBase + c4 * 4]) = v;
            }
        }
    }
}

// ================= channel mix v2: reg-cached Z, cp.async W double buffer =================
// 256 threads: two o-groups of 128 (og = t>>7 handles o in [og*16, og*16+16)).
__global__ void __launch_bounds__(256, 2) chanmix(const float* __restrict__ Z,
                                                  const float* __restrict__ w1re,
                                                  const float* __restrict__ w1im,
                                                  const float* __restrict__ w4re,
                                                  const float* __restrict__ w4im) {
    __shared__ float Zs[2][4][32][32];        // 32 KB
    __shared__ float Ws[2][2][2][32][32];     // [grp][buf][plane][i][y] 32 KB
    const int t = threadIdx.x;
    const int p = blockIdx.x >> 6;
    const int j = blockIdx.x & 63;
    const int x = j & 31;
    const float* wre = (j < 32) ? w1re : w4re;
    const float* wim = (j < 32) ? w1im : w4im;

    // load Z tile: 2048 float4 over 256 threads
#pragma unroll
    for (int pass = 0; pass < 8; ++pass) {
        int f = t + pass * 256;
        int plane = f >> 10;
        int rem = f & 1023;
        int bi = rem >> 3;
        int y4 = rem & 7;
        float4 v = *reinterpret_cast<const float4*>(
            &Z[(size_t)(plane * 64 + j) * 32768 + (size_t)(p * 128 + bi) * 32 + y4 * 4]);
        *reinterpret_cast<float4*>(&Zs[plane][bi >> 5][bi & 31][y4 * 4]) = v;
    }
    __syncthreads();

    const int og = t >> 7;
    const int t2 = t & 127;
    const int bb = (t2 >> 5) & 3;
    const int y  = t & 31;

    // register-cache Z for this (bb, y) — reused across all 16 o's
    float zre[32], zim[32];
#pragma unroll
    for (int i = 0; i < 32; ++i) {
        zre[i] = Zs[0][bb][i][y];
        zim[i] = Zs[1][bb][i][y];
    }

    auto fetchW = [&](int o, int buf) {
#pragma unroll
        for (int pass = 0; pass < 4; ++pass) {
            int f = t2 + pass * 128;
            int plane = f >> 8;
            int i = (f >> 3) & 31;
            int seg = f & 7;
            const float* wp = plane ? wim : wre;
            const float* g = &wp[((((size_t)(i * 32 + o)) * 8 + p) * 32 + x) * 32 + seg * 4];
            cpa16(smem_u32(&Ws[og][buf][plane][i][seg * 4]), g);
        }
    };

    fetchW(og * 16, 0);
    CPA_COMMIT();
    CPA_WAIT0();
    __syncthreads();

#pragma unroll 1
    for (int ol = 0; ol < 16; ++ol) {
        const int o = og * 16 + ol;
        const bool more = (ol + 1 < 16);
        if (more) {
            fetchW(o + 1, (ol + 1) & 1);
            CPA_COMMIT();
        }
        const int buf = ol & 1;
        float accre = 0.f, accim = 0.f;
#pragma unroll
        for (int i = 0; i < 32; ++i) {
            float wr = Ws[og][buf][0][i][y];
            float wi = Ws[og][buf][1][i][y];
            accre += zre[i] * wr - zim[i] * wi;
            accim += zre[i] * wi + zim[i] * wr;
        }
        size_t col = (size_t)(p * 128 + bb * 32 + o) * 32 + y;
        ushort_t hr, lr, hi2, li;
        bsplit(accre, hr, lr);
        bsplit(accim, hi2, li);
        g_Z3h[(size_t)j * 32768 + col]        = hr;
        g_Z3l[(size_t)j * 32768 + col]        = lr;
        g_Z3h[(size_t)(64 + j) * 32768 + col] = hi2;
        g_Z3l[(size_t)(64 + j) * 32768 + col] = li;
        if (more) {
            CPA_WAIT0();
            __syncthreads();
        }
    }
}

// ================= launch =================
extern "C" void kernel_launch(void* const* d_in, const int* in_sizes, int n_in,
                              void* d_out, int out_size) {
    const float* x    = (const float*)d_in[0];
    const float* w1re = (const float*)d_in[1];
    const float* w1im = (const float*)d_in[2];
    const float* w4re = (const float*)d_in[3];
    const float* w4im = (const float*)d_in[4];
    float* out = (float*)d_out;

    void *pYh, *pYl, *pZ, *pZ3h, *pZ3l, *pVh, *pVl;
    void *pT1h, *pT1l, *pA2h, *pA2l, *pA4h, *pA4l, *pT5h, *pT5l;
    cudaGetSymbolAddress(&pYh,  g_Yh);
    cudaGetSymbolAddress(&pYl,  g_Yl);
    cudaGetSymbolAddress(&pZ,   g_Z);
    cudaGetSymbolAddress(&pZ3h, g_Z3h);
    cudaGetSymbolAddress(&pZ3l, g_Z3l);
    cudaGetSymbolAddress(&pVh,  g_Vh);
    cudaGetSymbolAddress(&pVl,  g_Vl);
    cudaGetSymbolAddress(&pT1h, g_T1h);
    cudaGetSymbolAddress(&pT1l, g_T1l);
    cudaGetSymbolAddress(&pA2h, g_A2h);
    cudaGetSymbolAddress(&pA2l, g_A2l);
    cudaGetSymbolAddress(&pA4h, g_A4h);
    cudaGetSymbolAddress(&pA4l, g_A4l);
    cudaGetSymbolAddress(&pT5h, g_T5h);
    cudaGetSymbolAddress(&pT5l, g_T5l);

    // smem: SBUF = 2*BM*(BK+8)*2 + 2*BK*(BN+8)*2 ; double-buffered when KT>1
    auto s1k = mgemm<128, 64, 64, 4, 2, 256L, 64L, 0, 1>;      // 2*55296 = 110592
    auto s2k = mgemm<128, 64, 64, 4, 2, 512L, 32768L, 1, 0>;   // 110592
    auto s4k = mgemm<128, 64, 64, 4, 2, 128L, 32768L, 1, 2>;   // 110592
    auto s5k = mgemm<64, 128, 64, 2, 4, 64L, 256L, 1, 3>;      // 53248 (KT=1)
    cudaFuncSetAttribute(s1k, cudaFuncAttributeMaxDynamicSharedMemorySize, 110592);
    cudaFuncSetAttribute(s2k, cudaFuncAttributeMaxDynamicSharedMemorySize, 110592);
    cudaFuncSetAttribute(s4k, cudaFuncAttributeMaxDynamicSharedMemorySize, 110592);
    cudaFuncSetAttribute(s5k, cudaFuncAttributeMaxDynamicSharedMemorySize, 53248);

    init_tables<<<256, 256>>>();

    // S1: Y(262144x64) = x(262144x256) * T1(256x64) -> Y hi/lo plane scatter
    s1k<<<dim3(2048, 1), 256, 110592>>>(x, nullptr, nullptr,
                                        (const ushort_t*)pT1h, (const ushort_t*)pT1l, nullptr);

    // S2: Z(128x32768) = A2(128x512) * Y(512x32768)
    s2k<<<dim3(1, 512), 256, 110592>>>(nullptr, (const ushort_t*)pA2h, (const ushort_t*)pA2l,
                                       (const ushort_t*)pYh, (const ushort_t*)pYl, (float*)pZ);

    // S3: channel mixing (emits Z3 hi/lo)
    chanmix<<<512, 256>>>((const float*)pZ, w1re, w1im, w4re, w4im);

    // S4: V(512x32768) = A4(512x128) * Z3(128x32768) -> V hi/lo emit
    s4k<<<dim3(4, 512), 256, 110592>>>(nullptr, (const ushort_t*)pA4h, (const ushort_t*)pA4l,
                                       (const ushort_t*)pZ3h, (const ushort_t*)pZ3l, nullptr);

    // S5: out(262144x256) = V(262144x64) * T5(64x256)
    s5k<<<dim3(4096, 2), 256, 53248>>>(nullptr, (const ushort_t*)pVh, (const ushort_t*)pVl,
                                       (const ushort_t*)pT5h, (const ushort_t*)pT5l, out);
}

// round 10
// speedup vs baseline: 2.4152x; 1.2871x over previous
#include <cuda_runtime.h>
#include <cuda_fp16.h>
#include <cstdint>

// P=8, B=4, C=32, H=256, W=256, M1=M2=32
// rows R = P*B*C*H = 262144 ; pbc = P*B*C = 1024 ; cols (pbc,y) = 32768

typedef unsigned short ushort_t;

// ================= helpers =================
__device__ __forceinline__ uint32_t smem_u32(const void* p) {
    uint32_t a;
    asm("{ .reg .u64 t; cvta.to.shared.u64 t, %1; cvt.u32.u64 %0, t; }" : "=r"(a) : "l"(p));
    return a;
}
__device__ __forceinline__ void ldm4(uint32_t* r, uint32_t a) {
    asm volatile("ldmatrix.sync.aligned.m8n8.x4.shared.b16 {%0,%1,%2,%3}, [%4];"
                 : "=r"(r[0]), "=r"(r[1]), "=r"(r[2]), "=r"(r[3]) : "r"(a));
}
__device__ __forceinline__ void ldm4t(uint32_t* r, uint32_t a) {
    asm volatile("ldmatrix.sync.aligned.m8n8.x4.trans.shared.b16 {%0,%1,%2,%3}, [%4];"
                 : "=r"(r[0]), "=r"(r[1]), "=r"(r[2]), "=r"(r[3]) : "r"(a));
}
__device__ __forceinline__ void mma16816(float* c, const uint32_t* a, const uint32_t* b) {
    asm volatile("mma.sync.aligned.m16n8k16.row.col.f32.f16.f16.f32 "
                 "{%0,%1,%2,%3}, {%4,%5,%6,%7}, {%8,%9}, {%0,%1,%2,%3};"
                 : "+f"(c[0]), "+f"(c[1]), "+f"(c[2]), "+f"(c[3])
                 : "r"(a[0]), "r"(a[1]), "r"(a[2]), "r"(a[3]), "r"(b[0]), "r"(b[1]));
}
__device__ __forceinline__ void hsplit(float v, ushort_t& h, ushort_t& l) {
    __half hh = __float2half_rn(v);
    __half hl = __float2half_rn(v - __half2float(hh));
    h = __half_as_ushort(hh);
    l = __half_as_ushort(hl);
}
__device__ __forceinline__ ushort_t h1(float v) {
    return __half_as_ushort(__float2half_rn(v));
}
__device__ __forceinline__ void cpa16(uint32_t saddr, const void* g) {
    asm volatile("cp.async.cg.shared.global [%0], [%1], 16;" :: "r"(saddr), "l"(g));
}
#define CPA_COMMIT() asm volatile("cp.async.commit_group;" ::: "memory")
#define CPA_WAIT0()  asm volatile("cp.async.wait_group 0;" ::: "memory")

// ================= scratch =================
__device__ __align__(16) ushort_t g_Y [512u * 32768];       // fp16 [plane*256+h][pbc*32+y]
__device__ __align__(16) float    g_Z [128u * 32768];       // fp32 [plane*64+j][col]
__device__ __align__(16) ushort_t g_Z3[128u * 32768];       // fp16
__device__ __align__(16) ushort_t g_V [262144u * 64];       // fp16 [row][plane*32+y]
__device__ __align__(16) ushort_t g_T1h[256 * 64], g_T1l[256 * 64];    // [k=w][n]
__device__ __align__(16) ushort_t g_A2h[128 * 512], g_A2l[128 * 512];  // [row][k]
__device__ __align__(16) ushort_t g_A4h[512 * 128], g_A4l[512 * 128];  // [row][k]
__device__ __align__(16) ushort_t g_T5h[64 * 256], g_T5l[64 * 256];    // [k][n=w] UNSCALED (c_k)

// ================= table init (pre-split to fp16 hi/lo) =================
__global__ void init_tables() {
    int t = blockIdx.x * 256 + threadIdx.x;   // 0..65535
    ushort_t h, l;
    if (t < 256 * 64) {     // T1 [w][c]: c<32 cos, c>=32 -sin
        int w = t >> 6, c = t & 63, y = c & 31;
        int m = (w * y) & 255;
        double s, ct; sincospi(2.0 * m / 256.0, &s, &ct);
        hsplit((c < 32) ? (float)ct : (float)(-s), h, l);
        g_T1h[t] = h; g_T1l[t] = l;
    }
    {                       // A2 128x512
        int r = t >> 9, k = t & 511;
        int pk = k >> 8, hh = k & 255;
        int j = r & 63;
        int xr = (j < 32) ? j : (192 + j);
        int m = (xr * hh) & 255;
        double s, ct; sincospi(2.0 * m / 256.0, &s, &ct);
        float v;
        if (r < 64) v = (pk == 0) ? (float)ct : (float)s;
        else        v = (pk == 0) ? (float)(-s) : (float)ct;
        hsplit(v, h, l);
        g_A2h[t] = h; g_A2l[t] = l;
    }
    {                       // A4 512x128
        int r = t >> 7, c = t & 127;
        int pr = r >> 8, hh = r & 255;
        int pc = c >> 6, j = c & 63;
        int xr = (j < 32) ? j : (192 + j);
        int m = (xr * hh) & 255;
        double s, ct; sincospi(2.0 * m / 256.0, &s, &ct);
        float v;
        if (pr == 0) v = (pc == 0) ? (float)ct : (float)(-s);
        else         v = (pc == 0) ? (float)s  : (float)ct;
        hsplit(v, h, l);
        g_A4h[t] = h; g_A4l[t] = l;
    }
    if (t < 64 * 256) {     // T5 [k|32+k][w], UNSCALED: c_k cos / -c_k sin  (scale in S5 epi)
        int r = t >> 8, w = t & 255, k = r & 31;
        int m = (k * w) & 255;
        double s, ct; sincospi(2.0 * m / 256.0, &s, &ct);
        double coef = (k == 0) ? 1.0 : 2.0;
        hsplit((r < 32) ? (float)(coef * ct) : (float)(-coef * s), h, l);
        g_T5h[t] = h; g_T5l[t] = l;
    }
}

// ================= double-buffered cp.async fp16 2-pass warp-MMA GEMM =================
// C(M x NTOT) = A(M x KDIM) * B(KDIM x NTOT).
// AMODE 0: A fp32 data -> single fp16 in-kernel; B pre-split hi/lo (cp.async).
// AMODE 1: A pre-split hi/lo (cp.async); B single fp16 (cp.async).
// AMODE 2: A single fp16 (cp.async); B pre-split hi/lo (cp.async).
// CMODE 0: row-major f32.  CMODE 1: -> g_Y fp16 plane scatter (staged).
// CMODE 2: -> g_V fp16 emit.  CMODE 3: row-major f32 staged, scaled by 1/65536.
template<int BM, int BN, int BK, int WM, int WN, long KDIM, long NTOT,
         int AMODE, int CMODE>
__global__ void __launch_bounds__(256, 2) mgemm(
    const float* __restrict__ Af, const ushort_t* __restrict__ Ahg,
    const ushort_t* __restrict__ Alg,
    const ushort_t* __restrict__ Bhg, const ushort_t* __restrict__ Blg,
    float* __restrict__ Cf)
{
    constexpr int TWM = BM / WM, TWN = BN / WN, MT = TWM / 16, NT = TWN / 8;
    constexpr int APL = (AMODE == 1) ? 2 : 1;   // A smem planes
    constexpr int BPL = 3 - APL;                // B smem planes
    constexpr int BKP = BK + 8, BNP = BN + 8;
    constexpr int PA = BM * BKP * 2;            // bytes per A plane
    constexpr int PB = BK * BNP * 2;            // bytes per B plane
    constexpr int OA0 = 0, OA1 = PA;
    constexpr int OB0 = APL * PA, OB1 = OB0 + PB;
    constexpr int SBUF = APL * PA + BPL * PB;
    constexpr long KT = KDIM / BK;
    constexpr int NBUF = (KT > 1) ? 2 : 1;
    constexpr int AF4 = BM * BK / 1024;         // float4/thread (AMODE 0)
    constexpr int AF8 = BM * BK / 2048;         // 16B cp.async/thread per A plane
    constexpr int BF8 = BK * BN / 2048;
    static_assert(WM * WN == 8 && (NT % 2) == 0, "cfg");

    extern __shared__ char smem[];
    const uint32_t sb = smem_u32(smem);
    const int t = threadIdx.x, wid = t >> 5, lane = t & 31;
    const int wm = wid / WN, wn = wid % WN;
    const long rowBase = (long)blockIdx.x * BM;
    const long colBase = (long)blockIdx.y * BN;

    float4 aReg[AMODE == 0 ? AF4 : 1];
    float  acc[MT][NT][4];
#pragma unroll
    for (int i = 0; i < MT; ++i)
#pragma unroll
        for (int j = 0; j < NT; ++j)
#pragma unroll
            for (int q = 0; q < 4; ++q) acc[i][j][q] = 0.f;

    auto fetchAsync = [&](long k0, int buf) {
        const uint32_t bb = sb + buf * SBUF;
        if constexpr (AMODE == 1) {
#pragma unroll
            for (int f8 = 0; f8 < AF8; ++f8) {
                int f = t + f8 * 256;
                int ar = f / (BK / 8), ac8 = f % (BK / 8);
                uint32_t off = (uint32_t)(ar * BKP + ac8 * 8) * 2;
                cpa16(bb + OA0 + off, &Ahg[(rowBase + ar) * KDIM + k0 + ac8 * 8]);
                cpa16(bb + OA1 + off, &Alg[(rowBase + ar) * KDIM + k0 + ac8 * 8]);
            }
        } else if constexpr (AMODE == 2) {
#pragma unroll
            for (int f8 = 0; f8 < AF8; ++f8) {
                int f = t + f8 * 256;
                int ar = f / (BK / 8), ac8 = f % (BK / 8);
                uint32_t off = (uint32_t)(ar * BKP + ac8 * 8) * 2;
                cpa16(bb + OA0 + off, &Ahg[(rowBase + ar) * KDIM + k0 + ac8 * 8]);
            }
        }
#pragma unroll
        for (int f8 = 0; f8 < BF8; ++f8) {
            int f = t + f8 * 256;
            int br = f / (BN / 8), bc8 = f % (BN / 8);
            uint32_t off = (uint32_t)(br * BNP + bc8 * 8) * 2;
            cpa16(bb + OB0 + off, &Bhg[(k0 + br) * NTOT + colBase + bc8 * 8]);
            if constexpr (BPL == 2)
                cpa16(bb + OB1 + off, &Blg[(k0 + br) * NTOT + colBase + bc8 * 8]);
        }
    };
    auto loadA = [&](long k0) {   // AMODE 0 only
#pragma unroll
        for (int f4 = 0; f4 < AF4; ++f4) {
            int f = t + f4 * 256;
            int ar = f / (BK / 4), ac = f % (BK / 4);
            aReg[f4] = *reinterpret_cast<const float4*>(
                &Af[(rowBase + ar) * KDIM + k0 + ac * 4]);
        }
    };
    auto storeA = [&](int buf) {  // AMODE 0 only: convert to single fp16
#pragma unroll
        for (int f4 = 0; f4 < AF4; ++f4) {
            int f = t + f4 * 256;
            int ar = f / (BK / 4), ac = f % (BK / 4);
            ushort_t q0 = h1(aReg[f4].x), q1 = h1(aReg[f4].y);
            ushort_t q2 = h1(aReg[f4].z), q3 = h1(aReg[f4].w);
            uint32_t off = buf * SBUF + (uint32_t)(ar * BKP + ac * 4) * 2;
            *reinterpret_cast<uint2*>(smem + OA0 + off) =
                make_uint2(q0 | ((uint32_t)q1 << 16), q2 | ((uint32_t)q3 << 16));
        }
    };
    auto compute = [&](int buf) {
        const uint32_t bb = sb + buf * SBUF;
#pragma unroll
        for (int ks = 0; ks < BK / 16; ++ks) {
            const int k0 = ks * 16;
            uint32_t a0[MT][4], a1[MT][4];
#pragma unroll
            for (int i = 0; i < MT; ++i) {
                int row = wm * TWM + i * 16 + (lane & 15);
                int col = k0 + ((lane >> 4) << 3);
                uint32_t off = (uint32_t)(row * BKP + col) * 2;
                ldm4(a0[i], bb + OA0 + off);
                if constexpr (APL == 2) ldm4(a1[i], bb + OA1 + off);
            }
#pragma unroll
            for (int pr = 0; pr < NT / 2; ++pr) {
                uint32_t b0[4], b1[4];
                int krow = k0 + ((lane >> 3) & 1) * 8 + (lane & 7);
                int coln = wn * TWN + (pr * 2 + (lane >> 4)) * 8;
                uint32_t boff = (uint32_t)(krow * BNP + coln) * 2;
                ldm4t(b0, bb + OB0 + boff);
                if constexpr (BPL == 2) ldm4t(b1, bb + OB1 + boff);
#pragma unroll
                for (int i = 0; i < MT; ++i)
#pragma unroll
                    for (int nn = 0; nn < 2; ++nn) {
                        float* c = acc[i][pr * 2 + nn];
                        if constexpr (APL == 2) {
                            mma16816(c, a0[i], b0 + nn * 2);
                            mma16816(c, a1[i], b0 + nn * 2);
                        } else {
                            mma16816(c, a0[i], b0 + nn * 2);
                            mma16816(c, a0[i], b1 + nn * 2);
                        }
                    }
            }
        }
    };

    // prologue
    fetchAsync(0, 0);
    CPA_COMMIT();
    if constexpr (AMODE == 0) loadA(0);
    CPA_WAIT0();
    if constexpr (AMODE == 0) storeA(0);
    __syncthreads();

#pragma unroll 1
    for (long kt = 0; kt < KT; ++kt) {
        const int cur = (int)(kt % NBUF);
        const bool more = (kt + 1 < KT);
        if (more) {
            fetchAsync((kt + 1) * BK, cur ^ 1);
            CPA_COMMIT();
            if constexpr (AMODE == 0) loadA((kt + 1) * BK);
        }
        compute(cur);
        if (more) {
            if constexpr (AMODE == 0) storeA(cur ^ 1);
            CPA_WAIT0();
            __syncthreads();
        }
    }

    const int g = lane >> 2, tq = lane & 3;
    if constexpr (CMODE == 0) {
#pragma unroll
        for (int i = 0; i < MT; ++i)
#pragma unroll
            for (int j = 0; j < NT; ++j) {
                const float* c = acc[i][j];
                long r0 = rowBase + wm * TWM + i * 16 + g;
                long c0 = colBase + wn * TWN + j * 8 + tq * 2;
                *reinterpret_cast<float2*>(&Cf[r0 * NTOT + c0])       = make_float2(c[0], c[1]);
                *reinterpret_cast<float2*>(&Cf[(r0 + 8) * NTOT + c0]) = make_float2(c[2], c[3]);
            }
    } else if constexpr (CMODE == 2) {
#pragma unroll
        for (int i = 0; i < MT; ++i)
#pragma unroll
            for (int j = 0; j < NT; ++j) {
                const float* c = acc[i][j];
                long r0 = rowBase + wm * TWM + i * 16 + g;
                long c0 = colBase + wn * TWN + j * 8 + tq * 2;
                long pbc = c0 >> 5, y = c0 & 31;
#pragma unroll
                for (int rr = 0; rr < 2; ++rr) {
                    long r = r0 + rr * 8;
                    long plane = r >> 8, h = r & 255;
                    long addr = (pbc * 256 + h) * 64 + plane * 32 + y;
                    ushort_t q0 = h1(c[rr * 2]), q1 = h1(c[rr * 2 + 1]);
                    *reinterpret_cast<uint32_t*>(&g_V[addr]) = q0 | ((uint32_t)q1 << 16);
                }
            }
    } else {
        // staged: CMODE 1 (Y fp16 plane scatter) / CMODE 3 (f32 row-major scaled)
        float* stage = reinterpret_cast<float*>(smem);
        __syncthreads();
#pragma unroll
        for (int i = 0; i < MT; ++i)
#pragma unroll
            for (int j = 0; j < NT; ++j) {
                const float* c = acc[i][j];
                int row = wm * TWM + i * 16 + g;
                int col = wn * TWN + j * 8 + tq * 2;
                *reinterpret_cast<float2*>(&stage[row * (BN + 4) + col])       = make_float2(c[0], c[1]);
                *reinterpret_cast<float2*>(&stage[(row + 8) * (BN + 4) + col]) = make_float2(c[2], c[3]);
            }
        __syncthreads();
        if constexpr (CMODE == 1) {
            const long pbc = rowBase >> 8;
            const int hb = (int)(rowBase & 255);
#pragma unroll
            for (int it = 0; it < BM * BN / 1024; ++it) {
                int idx = t + it * 256;
                int r = idx / (BN / 4), c4 = idx % (BN / 4);
                float4 v = *reinterpret_cast<float4*>(&stage[r * (BN + 4) + c4 * 4]);
                int c = c4 * 4, plane = c >> 5, y = c & 31;
                ushort_t q0 = h1(v.x), q1 = h1(v.y), q2 = h1(v.z), q3 = h1(v.w);
                long addr = (long)(plane * 256 + hb + r) * 32768L + pbc * 32 + y;
                *reinterpret_cast<uint2*>(&g_Y[addr]) =
                    make_uint2(q0 | ((uint32_t)q1 << 16), q2 | ((uint32_t)q3 << 16));
            }
        } else {
#pragma unroll
            for (int it = 0; it < BM * BN / 1024; ++it) {
                int idx = t + it * 256;
                int r = idx / (BN / 4), c4 = idx % (BN / 4);
                float4 v = *reinterpret_cast<float4*>(&stage[r * (BN + 4) + c4 * 4]);
                constexpr float SC = 1.0f / 65536.0f;
                v.x *= SC; v.y *= SC; v.z *= SC; v.w *= SC;
                *reinterpret_cast<float4*>(&Cf[(rowBase + r) * NTOT + colBase + c4 * 4]) = v;
            }
        }
    }
}

// ================= channel mix: reg-cached Z, cp.async W double buffer, fp16 out =================
__global__ void __launch_bounds__(256, 2) chanmix(const float* __restrict__ Z,
                                                  const float* __restrict__ w1re,
                                                  const float* __restrict__ w1im,
                                                  const float* __restrict__ w4re,
                                                  const float* __restrict__ w4im) {
    __shared__ float Zs[2][4][32][32];        // 32 KB
    __shared__ float Ws[2][2][2][32][32];     // [grp][buf][plane][i][y] 32 KB
    const int t = threadIdx.x;
    const int p = blockIdx.x >> 6;
    const int j = blockIdx.x & 63;
    const int x = j & 31;
    const float* wre = (j < 32) ? w1re : w4re;
    const float* wim = (j < 32) ? w1im : w4im;

#pragma unroll
    for (int pass = 0; pass < 8; ++pass) {
        int f = t + pass * 256;
        int plane = f >> 10;
        int rem = f & 1023;
        int bi = rem >> 3;
        int y4 = rem & 7;
        float4 v = *reinterpret_cast<const float4*>(
            &Z[(size_t)(plane * 64 + j) * 32768 + (size_t)(p * 128 + bi) * 32 + y4 * 4]);
        *reinterpret_cast<float4*>(&Zs[plane][bi >> 5][bi & 31][y4 * 4]) = v;
    }
    __syncthreads();

    const int og = t >> 7;
    const int t2 = t & 127;
    const int bb = (t2 >> 5) & 3;
    const int y  = t & 31;

    float zre[32], zim[32];
#pragma unroll
    for (int i = 0; i < 32; ++i) {
        zre[i] = Zs[0][bb][i][y];
        zim[i] = Zs[1][bb][i][y];
    }

    auto fetchW = [&](int o, int buf) {
#pragma unroll
        for (int pass = 0; pass < 4; ++pass) {
            int f = t2 + pass * 128;
            int plane = f >> 8;
            int i = (f >> 3) & 31;
            int seg = f & 7;
            const float* wp = plane ? wim : wre;
            const float* g = &wp[((((size_t)(i * 32 + o)) * 8 + p) * 32 + x) * 32 + seg * 4];
            cpa16(smem_u32(&Ws[og][buf][plane][i][seg * 4]), g);
        }
    };

    fetchW(og * 16, 0);
    CPA_COMMIT();
    CPA_WAIT0();
    __syncthreads();

#pragma unroll 1
    for (int ol = 0; ol < 16; ++ol) {
        const int o = og * 16 + ol;
        const bool more = (ol + 1 < 16);
        if (more) {
            fetchW(o + 1, (ol + 1) & 1);
            CPA_COMMIT();
        }
        const int buf = ol & 1;
        float accre = 0.f, accim = 0.f;
#pragma unroll
        for (int i = 0; i < 32; ++i) {
            float wr = Ws[og][buf][0][i][y];
            float wi = Ws[og][buf][1][i][y];
            accre += zre[i] * wr - zim[i] * wi;
            accim += zre[i] * wi + zim[i] * wr;
        }
        size_t col = (size_t)(p * 128 + bb * 32 + o) * 32 + y;
        g_Z3[(size_t)j * 32768 + col]        = h1(accre);
        g_Z3[(size_t)(64 + j) * 32768 + col] = h1(accim);
        if (more) {
            CPA_WAIT0();
            __syncthreads();
        }
    }
}

// ================= launch =================
extern "C" void kernel_launch(void* const* d_in, const int* in_sizes, int n_in,
                              void* d_out, int out_size) {
    const float* x    = (const float*)d_in[0];
    const float* w1re = (const float*)d_in[1];
    const float* w1im = (const float*)d_in[2];
    const float* w4re = (const float*)d_in[3];
    const float* w4im = (const float*)d_in[4];
    float* out = (float*)d_out;

    void *pY, *pZ, *pZ3, *pV;
    void *pT1h, *pT1l, *pA2h, *pA2l, *pA4h, *pA4l, *pT5h, *pT5l;
    cudaGetSymbolAddress(&pY,   g_Y);
    cudaGetSymbolAddress(&pZ,   g_Z);
    cudaGetSymbolAddress(&pZ3,  g_Z3);
    cudaGetSymbolAddress(&pV,   g_V);
    cudaGetSymbolAddress(&pT1h, g_T1h);
    cudaGetSymbolAddress(&pT1l, g_T1l);
    cudaGetSymbolAddress(&pA2h, g_A2h);
    cudaGetSymbolAddress(&pA2l, g_A2l);
    cudaGetSymbolAddress(&pA4h, g_A4h);
    cudaGetSymbolAddress(&pA4l, g_A4l);
    cudaGetSymbolAddress(&pT5h, g_T5h);
    cudaGetSymbolAddress(&pT5l, g_T5l);

    // S1: A = x fp32 -> fp16 single; B = T1 split.   smem/buf = PA + 2*PB = 18432+18432
    auto s1k = mgemm<128, 64, 64, 4, 2, 256L, 64L, 0, 1>;
    // S2: A = A2 split; B = Y single.                smem/buf = 2*18432 + 9216
    auto s2k = mgemm<128, 64, 64, 4, 2, 512L, 32768L, 1, 0>;
    // S4: A = A4 split; B = Z3 single.
    auto s4k = mgemm<128, 64, 64, 4, 2, 128L, 32768L, 1, 2>;
    // S5: A = V single; B = T5 split.                smem = 9216 + 2*17408 (KT=1)
    auto s5k = mgemm<64, 128, 64, 2, 4, 64L, 256L, 2, 3>;
    cudaFuncSetAttribute(s1k, cudaFuncAttributeMaxDynamicSharedMemorySize, 73728);
    cudaFuncSetAttribute(s2k, cudaFuncAttributeMaxDynamicSharedMemorySize, 92160);
    cudaFuncSetAttribute(s4k, cudaFuncAttributeMaxDynamicSharedMemorySize, 92160);
    cudaFuncSetAttribute(s5k, cudaFuncAttributeMaxDynamicSharedMemorySize, 44032);

    init_tables<<<256, 256>>>();

    // S1: Y(262144x64) = x(262144x256) * T1(256x64) -> Y fp16 plane scatter
    s1k<<<dim3(2048, 1), 256, 73728>>>(x, nullptr, nullptr,
                                       (const ushort_t*)pT1h, (const ushort_t*)pT1l, nullptr);

    // S2: Z(128x32768) = A2(128x512) * Y(512x32768) -> fp32
    s2k<<<dim3(1, 512), 256, 92160>>>(nullptr, (const ushort_t*)pA2h, (const ushort_t*)pA2l,
                                      (const ushort_t*)pY, nullptr, (float*)pZ);

    // S3: channel mixing (emits Z3 fp16)
    chanmix<<<512, 256>>>((const float*)pZ, w1re, w1im, w4re, w4im);

    // S4: V(512x32768) = A4(512x128) * Z3(128x32768) -> V fp16 emit
    s4k<<<dim3(4, 512), 256, 92160>>>(nullptr, (const ushort_t*)pA4h, (const ushort_t*)pA4l,
                                      (const ushort_t*)pZ3, nullptr, nullptr);

    // S5: out(262144x256) = V(262144x64) * T5(64x256), scaled 1/65536 in epilogue
    s5k<<<dim3(4096, 2), 256, 44032>>>(nullptr, (const ushort_t*)pV, nullptr,
                                       (const ushort_t*)pT5h, (const ushort_t*)pT5l, out);
}